// round 8
// baseline (speedup 1.0000x reference)
#include <cuda_runtime.h>
#include <cuda_bf16.h>

#define X_CH   256
#define Y_CH   512
#define DIM    128
#define NHEAD  4
#define HD     32
#define HWX    4096
#define HWY    1024
#define BATCH  2
#define GAMMA  0.17677669529663687f   // 32^-0.5

typedef __nv_bfloat16 bf16;

// ---------------- scratch (device globals; no allocation) ----------------
static __device__ __align__(16) bf16 g_qxh[BATCH*NHEAD*HWX*HD], g_qxl[BATCH*NHEAD*HWX*HD];
static __device__ __align__(16) bf16 g_kxh[BATCH*NHEAD*HWX*HD], g_kxl[BATCH*NHEAD*HWX*HD];
static __device__ __align__(16) bf16 g_vxh[BATCH*NHEAD*HWX*HD], g_vxl[BATCH*NHEAD*HWX*HD];
static __device__ __align__(16) bf16 g_qyh[BATCH*NHEAD*HWY*HD], g_qyl[BATCH*NHEAD*HWY*HD];
static __device__ __align__(16) bf16 g_kyh[BATCH*NHEAD*HWY*HD], g_kyl[BATCH*NHEAD*HWY*HD];
static __device__ __align__(16) bf16 g_vyh[BATCH*NHEAD*HWY*HD], g_vyl[BATCH*NHEAD*HWY*HD];
static __device__ float g_ax[BATCH*NHEAD*HWX*HD];   // attention out [b,h,p,d]
static __device__ float g_ay[BATCH*NHEAD*HWY*HD];
// pre-split QKV weights, row-major [m][k]
static __device__ __align__(16) bf16 g_wxqh[384*X_CH], g_wxql[384*X_CH];
static __device__ __align__(16) bf16 g_wyqh[384*Y_CH], g_wyql[384*Y_CH];

__device__ __forceinline__ void bsplit(float v, bf16& h, bf16& l) {
    h = __float2bfloat16(v);
    l = __float2bfloat16(v - __bfloat162float(h));
}
__device__ __forceinline__ unsigned pack2(bf16 a, bf16 b) {
    return (unsigned)__bfloat16_as_ushort(a) | ((unsigned)__bfloat16_as_ushort(b) << 16);
}

// ---------------- prep: split QKV weights (elementwise, no transpose) -----
__global__ void __launch_bounds__(256) split_w_kernel(
    const float* __restrict__ s0, const float* __restrict__ s1)
{
    int e = (blockIdx.x * 256 + threadIdx.x) * 4;
    const float* s; bf16 *dh, *dl;
    if (e < 98304) { s = s0; dh = g_wxqh; dl = g_wxql; }
    else           { e -= 98304; s = s1; dh = g_wyqh; dl = g_wyql; }
    float4 v = *(const float4*)(s + e);
    bf16 h0,l0,h1,l1,h2,l2,h3,l3;
    bsplit(v.x,h0,l0); bsplit(v.y,h1,l1); bsplit(v.z,h2,l2); bsplit(v.w,h3,l3);
    *(uint2*)(dh + e) = make_uint2(pack2(h0,h1), pack2(h2,h3));
    *(uint2*)(dl + e) = make_uint2(pack2(l0,l1), pack2(l2,l3));
}

// ---------------- MMA helpers ----------------
__device__ __forceinline__ void ldsm4(unsigned r[4], const void* p) {
    unsigned a = (unsigned)__cvta_generic_to_shared(p);
    asm volatile("ldmatrix.sync.aligned.m8n8.x4.shared.b16 {%0,%1,%2,%3}, [%4];"
        : "=r"(r[0]), "=r"(r[1]), "=r"(r[2]), "=r"(r[3]) : "r"(a));
}
__device__ __forceinline__ void ldsm4t(unsigned r[4], const void* p) {
    unsigned a = (unsigned)__cvta_generic_to_shared(p);
    asm volatile("ldmatrix.sync.aligned.m8n8.x4.trans.shared.b16 {%0,%1,%2,%3}, [%4];"
        : "=r"(r[0]), "=r"(r[1]), "=r"(r[2]), "=r"(r[3]) : "r"(a));
}
__device__ __forceinline__ void mma16816(float c[4], const unsigned a[4],
                                         unsigned b0, unsigned b1) {
    asm volatile("mma.sync.aligned.m16n8k16.row.col.f32.bf16.bf16.f32 "
        "{%0,%1,%2,%3}, {%4,%5,%6,%7}, {%8,%9}, {%0,%1,%2,%3};"
        : "+f"(c[0]), "+f"(c[1]), "+f"(c[2]), "+f"(c[3])
        : "r"(a[0]), "r"(a[1]), "r"(a[2]), "r"(a[3]), "r"(b0), "r"(b1));
}

#define GSTR 40    // A tile row stride (bf16), [m][k]
#define BSTR 136   // B tile row stride (bf16), [k][n]

// ====== QKV tensor-core GEMM v3: pre-split W, reg-prefetched X ============
// blocks [0,48): y (K=512, first); [48,240): x.
__global__ void __launch_bounds__(256, 2) qkv_mma3_kernel(
    const float* __restrict__ Xx, const float* __restrict__ bx,
    const float* __restrict__ Xy, const float* __restrict__ by_)
{
    __shared__ __align__(16) char SMB[37888];
    bf16* As0 = (bf16*)SMB;
    bf16* As1 = As0 + 128*GSTR;
    bf16* Bs0 = As1 + 128*GSTR;
    bf16* Bs1 = Bs0 + 32*BSTR;
    float* Cst = (float*)SMB;           // 32KB fp32, reused post-mainloop

    const bf16 *Wh, *Wl;
    const float *X, *bias;
    bf16 *Qh_, *Ql_, *Kh_, *Kl_, *Vh_, *Vl_;
    int N, K, m0, n0, b;
    int blk = blockIdx.x;
    if (blk < 48) {
        N = HWY; K = Y_CH;
        b = blk / 24; int r = blk % 24; m0 = (r % 3) * 128; n0 = (r / 3) * 128;
        Wh = g_wyqh; Wl = g_wyql; X = Xy + (size_t)b * K * N; bias = by_;
        Qh_=g_qyh; Ql_=g_qyl; Kh_=g_kyh; Kl_=g_kyl; Vh_=g_vyh; Vl_=g_vyl;
    } else {
        blk -= 48;
        N = HWX; K = X_CH;
        b = blk / 96; int r = blk % 96; m0 = (r % 3) * 128; n0 = (r / 3) * 128;
        Wh = g_wxqh; Wl = g_wxql; X = Xx + (size_t)b * K * N; bias = bx;
        Qh_=g_qxh; Ql_=g_qxl; Kh_=g_kxh; Kl_=g_kxl; Vh_=g_vxh; Vl_=g_vxl;
    }

    const int tid = threadIdx.x, lane = tid & 31;
    const int w = tid >> 5;
    const int wm = w & 3, wn = w >> 2;
    const int arow = (lane & 7) + ((lane & 8) ? 8 : 0);
    const int acol = (lane & 16) ? 8 : 0;
    const int bkrow = (lane & 7) + ((lane & 8) ? 8 : 0);
    const int bncol = (lane & 16) ? 8 : 0;

    // staging geometry: A 16 bf16/thread/part; B 16 fp32/thread
    const int sa_row = tid >> 1, sa_col = (tid & 1) * 16;
    const int sb_f = tid * 16;
    const int sb_k = sb_f >> 7, sb_n = sb_f & 127;

    uint4 apre[2][2];
    float4 bpre[4];

    const int nkc = K >> 5;

    // prefetch chunk 0
    {
        const bf16* w0 = Wh + (size_t)(m0 + sa_row) * K + sa_col;
        const bf16* w1 = Wl + (size_t)(m0 + sa_row) * K + sa_col;
        apre[0][0] = *(const uint4*)(w0);  apre[0][1] = *(const uint4*)(w0 + 8);
        apre[1][0] = *(const uint4*)(w1);  apre[1][1] = *(const uint4*)(w1 + 8);
        const float* xs = X + (size_t)sb_k * N + n0 + sb_n;
        #pragma unroll
        for (int i = 0; i < 4; i++) bpre[i] = *(const float4*)(xs + i * 4);
    }

    float acc[2][8][4] = {};

    for (int kc = 0; kc < nkc; kc++) {
        __syncthreads();
        // store staged A (bf16 copy)
        *(uint4*)&As0[sa_row * GSTR + sa_col]     = apre[0][0];
        *(uint4*)&As0[sa_row * GSTR + sa_col + 8] = apre[0][1];
        *(uint4*)&As1[sa_row * GSTR + sa_col]     = apre[1][0];
        *(uint4*)&As1[sa_row * GSTR + sa_col + 8] = apre[1][1];
        // convert + store staged B
        #pragma unroll
        for (int i = 0; i < 4; i++) {
            bf16 h0,l0,h1,l1,h2,l2,h3,l3;
            bsplit(bpre[i].x,h0,l0); bsplit(bpre[i].y,h1,l1);
            bsplit(bpre[i].z,h2,l2); bsplit(bpre[i].w,h3,l3);
            *(uint2*)&Bs0[sb_k * BSTR + sb_n + i*4] = make_uint2(pack2(h0,h1), pack2(h2,h3));
            *(uint2*)&Bs1[sb_k * BSTR + sb_n + i*4] = make_uint2(pack2(l0,l1), pack2(l2,l3));
        }
        __syncthreads();

        // prefetch next chunk (overlaps MMA below)
        if (kc + 1 < nkc) {
            const bf16* w0 = Wh + (size_t)(m0 + sa_row) * K + (kc+1)*32 + sa_col;
            const bf16* w1 = Wl + (size_t)(m0 + sa_row) * K + (kc+1)*32 + sa_col;
            apre[0][0] = *(const uint4*)(w0);  apre[0][1] = *(const uint4*)(w0 + 8);
            apre[1][0] = *(const uint4*)(w1);  apre[1][1] = *(const uint4*)(w1 + 8);
            const float* xs = X + (size_t)((kc+1)*32 + sb_k) * N + n0 + sb_n;
            #pragma unroll
            for (int i = 0; i < 4; i++) bpre[i] = *(const float4*)(xs + i * 4);
        }

        #pragma unroll
        for (int ks = 0; ks < 2; ks++) {
            unsigned ah[2][4], al[2][4];
            #pragma unroll
            for (int im = 0; im < 2; im++) {
                ldsm4(ah[im], &As0[(wm*32 + im*16 + arow) * GSTR + ks*16 + acol]);
                ldsm4(al[im], &As1[(wm*32 + im*16 + arow) * GSTR + ks*16 + acol]);
            }
            #pragma unroll
            for (int jn = 0; jn < 4; jn++) {
                unsigned bh4[4], bl4[4];
                const int boff = (ks*16 + bkrow) * BSTR + wn*64 + jn*16 + bncol;
                ldsm4t(bh4, &Bs0[boff]);
                ldsm4t(bl4, &Bs1[boff]);
                #pragma unroll
                for (int im = 0; im < 2; im++) {
                    mma16816(acc[im][2*jn],   ah[im], bh4[0], bh4[1]);
                    mma16816(acc[im][2*jn],   al[im], bh4[0], bh4[1]);
                    mma16816(acc[im][2*jn],   ah[im], bl4[0], bl4[1]);
                    mma16816(acc[im][2*jn+1], ah[im], bh4[2], bh4[3]);
                    mma16816(acc[im][2*jn+1], al[im], bh4[2], bh4[3]);
                    mma16816(acc[im][2*jn+1], ah[im], bl4[2], bl4[3]);
                }
            }
        }
    }

    // staged epilogue (validated): fragments -> smem fp32 -> linear scatter
    const int r = lane >> 2, cq = (lane & 3) * 2;
    #pragma unroll
    for (int im = 0; im < 2; im++) {
        __syncthreads();
        #pragma unroll
        for (int j8 = 0; j8 < 8; j8++) {
            int col = wn*64 + j8*8 + cq;
            Cst[(wm*16 + r) * 128 + col]         = acc[im][j8][0];
            Cst[(wm*16 + r) * 128 + col + 1]     = acc[im][j8][1];
            Cst[(wm*16 + r + 8) * 128 + col]     = acc[im][j8][2];
            Cst[(wm*16 + r + 8) * 128 + col + 1] = acc[im][j8][3];
        }
        __syncthreads();
        for (int idx = tid; idx < 64*128; idx += 256) {
            int srow = idx >> 7, scol = idx & 127;
            int o = m0 + (srow >> 4) * 32 + im*16 + (srow & 15);
            int n = n0 + scol;
            float v = Cst[idx] + bias[o];
            int t = o >> 7, h = (o & 127) >> 5, d = o & 31;
            bf16 hh, ll;
            if (t == 0) {
                bsplit(v * GAMMA, hh, ll);
                size_t i2 = ((size_t)(b*NHEAD + h) * N + n) * HD + d;
                Qh_[i2] = hh;  Ql_[i2] = ll;
            } else if (t == 1) {
                bsplit(v, hh, ll);
                size_t i2 = ((size_t)(b*NHEAD + h) * N + n) * HD + d;
                Kh_[i2] = hh;  Kl_[i2] = ll;
            } else {
                bsplit(v, hh, ll);
                size_t i2 = ((size_t)(b*NHEAD + h) * HD + d) * N + n;
                Vh_[i2] = hh;  Vl_[i2] = ll;
            }
        }
    }
}

// ============ merged proj GEMM (fp32, validated round-6) ==================
__global__ void __launch_bounds__(256) gemm_proj_kernel(
    const float* __restrict__ Wx, const float* __restrict__ bpx, const float* __restrict__ Rx,
    const float* __restrict__ Wy, const float* __restrict__ bpy, const float* __restrict__ Ry,
    float* __restrict__ outp)
{
    const float *W, *bias, *Res, *Att;
    float* Out;
    int OC, N, b, m0, n0;
    int blk = blockIdx.x;
    if (blk < 256) {
        OC = Y_CH; N = HWY; W = Wy; bias = bpy; Res = Ry; Att = g_ay;
        Out = outp + (size_t)BATCH * X_CH * HWX;
        b = blk / 128; int r = blk % 128; m0 = (r % 8) * 64; n0 = (r / 8) * 64;
    } else {
        blk -= 256;
        OC = X_CH; N = HWX; W = Wx; bias = bpx; Res = Rx; Att = g_ax;
        Out = outp;
        b = blk / 256; int r = blk % 256; m0 = (r % 4) * 64; n0 = (r / 4) * 64;
    }

    __shared__ __align__(16) float As[16][64];
    __shared__ __align__(16) float Bs[16][64];

    const int tid = threadIdx.x;
    const int ty = tid >> 4, tx = tid & 15;
    const int am = tid >> 2, ak = (tid & 3) << 2;
    const int bn_ = tid >> 2, bkq = (tid & 3) << 2;

    float acc[4][4] = {};

    for (int k0 = 0; k0 < DIM; k0 += 16) {
        float4 av = *(const float4*)(W + (size_t)(m0 + am) * DIM + k0 + ak);
        int c = k0 + bkq;
        int h = c >> 5, d = c & 31;
        float4 bv = *(const float4*)(Att + ((size_t)(b * NHEAD + h) * N + n0 + bn_) * HD + d);
        As[ak+0][am] = av.x; As[ak+1][am] = av.y; As[ak+2][am] = av.z; As[ak+3][am] = av.w;
        Bs[bkq+0][bn_] = bv.x; Bs[bkq+1][bn_] = bv.y; Bs[bkq+2][bn_] = bv.z; Bs[bkq+3][bn_] = bv.w;
        __syncthreads();
        #pragma unroll
        for (int kk = 0; kk < 16; kk++) {
            float4 a4 = *(const float4*)(&As[kk][ty << 2]);
            float4 b4 = *(const float4*)(&Bs[kk][tx << 2]);
            float ar[4] = {a4.x, a4.y, a4.z, a4.w};
            float br[4] = {b4.x, b4.y, b4.z, b4.w};
            #pragma unroll
            for (int i = 0; i < 4; i++)
                #pragma unroll
                for (int j = 0; j < 4; j++)
                    acc[i][j] += ar[i] * br[j];
        }
        __syncthreads();
    }

    #pragma unroll
    for (int i = 0; i < 4; i++) {
        int o = m0 + (ty << 2) + i;
        float bval = bias[o];
        size_t off = ((size_t)b * OC + o) * N + n0 + (tx << 2);
        float4 rr = *(const float4*)(Res + off);
        float4 v;
        v.x = acc[i][0] + bval + rr.x;
        v.y = acc[i][1] + bval + rr.y;
        v.z = acc[i][2] + bval + rr.z;
        v.w = acc[i][3] + bval + rr.w;
        *(float4*)(Out + off) = v;
    }
}

// ====== MMA flash attention v2: 8 warps / 128 q per block, cp.async ========
__device__ __forceinline__ void cpasync16(unsigned dst, const void* src) {
    asm volatile("cp.async.ca.shared.global [%0], [%1], 16;" :: "r"(dst), "l"(src));
}

#define QSTR 40
#define VSTR 72
#define OFF_KH 0
#define OFF_KL 2560
#define OFF_VH 5120
#define OFF_VL 7424
#define STAGE_ELEMS 9728

// blocks [0,64): y attends x (64 iter each, first); [64,320): x attends y.
__global__ void __launch_bounds__(256) attn_mma_kernel()
{
    __shared__ __align__(16) bf16 KV[2][STAGE_ELEMS];

    int blk = blockIdx.x;
    const bf16 *Qh, *Ql, *Kh, *Kl, *Vh, *Vl; float* O;
    int NQ, NK, bh, q0;
    if (blk < 64) {    // dir1: y attends x
        bh = blk >> 3; q0 = (blk & 7) * 128; NQ = HWY; NK = HWX;
        Qh=g_qyh; Ql=g_qyl; Kh=g_kxh; Kl=g_kxl; Vh=g_vxh; Vl=g_vxl; O=g_ay;
    } else {           // dir0: x attends y
        blk -= 64;
        bh = blk >> 5; q0 = (blk & 31) * 128; NQ = HWX; NK = HWY;
        Qh=g_qxh; Ql=g_qxl; Kh=g_kyh; Kl=g_kyl; Vh=g_vyh; Vl=g_vyl; O=g_ax;
    }

    const int tid = threadIdx.x, w = tid >> 5, lane = tid & 31;
    const size_t kbase = (size_t)bh * NK * HD;
    const size_t vbase = (size_t)bh * HD * NK;
    const int nt = NK >> 6;

    // one 8-element chunk per thread (256 threads cover 2048-elem tiles)
    const int e0 = tid * 8;
    const int ks0 = (e0 >> 5) * QSTR + (e0 & 31);
    const int vs0 = (e0 >> 6) * VSTR + (e0 & 63);
    const size_t kg0 = (size_t)(e0 >> 5) * HD + (e0 & 31);
    const size_t vg0 = (size_t)(e0 >> 6) * NK + (e0 & 63);

    unsigned sb0 = (unsigned)__cvta_generic_to_shared(&KV[0][0]);
    unsigned sb1 = (unsigned)__cvta_generic_to_shared(&KV[1][0]);

    // issue tile 0 into stage 0
    cpasync16(sb0 + (OFF_KH + ks0) * 2, Kh + kbase + kg0);
    cpasync16(sb0 + (OFF_KL + ks0) * 2, Kl + kbase + kg0);
    cpasync16(sb0 + (OFF_VH + vs0) * 2, Vh + vbase + vg0);
    cpasync16(sb0 + (OFF_VL + vs0) * 2, Vl + vbase + vg0);
    asm volatile("cp.async.commit_group;");

    // Q fragments directly from global (m16n8k16 A-lane mapping)
    unsigned qf[2][2][4];
    {
        const size_t qrow = (size_t)bh * NQ * HD + (size_t)(q0 + w*16 + (lane >> 2)) * HD;
        const int qc = (lane & 3) * 2;
        #pragma unroll
        for (int p = 0; p < 2; p++) {
            const bf16* Qp = p ? Ql : Qh;
            #pragma unroll
            for (int c = 0; c < 2; c++) {
                const bf16* base = Qp + qrow + c*16 + qc;
                qf[p][c][0] = *(const unsigned*)(base);
                qf[p][c][1] = *(const unsigned*)(base + 8*HD);
                qf[p][c][2] = *(const unsigned*)(base + 8);
                qf[p][c][3] = *(const unsigned*)(base + 8*HD + 8);
            }
        }
    }

    const int brow = (lane & 7) + ((lane & 16) ? 8 : 0);
    const int bcol = (lane & 8) ? 8 : 0;

    float m0r = -1e30f, m1r = -1e30f, l0 = 0.f, l1 = 0.f;
    float oacc[4][4] = {};

    for (int kt = 0; kt < nt; kt++) {
        const int s = kt & 1;
        if (kt + 1 < nt) {
            unsigned sb = (s ^ 1) ? sb1 : sb0;
            size_t ka = kbase + (size_t)(kt + 1) * 64 * HD;
            size_t va = vbase + (size_t)(kt + 1) * 64;
            cpasync16(sb + (OFF_KH + ks0) * 2, Kh + ka + kg0);
            cpasync16(sb + (OFF_KL + ks0) * 2, Kl + ka + kg0);
            cpasync16(sb + (OFF_VH + vs0) * 2, Vh + va + vg0);
            cpasync16(sb + (OFF_VL + vs0) * 2, Vl + va + vg0);
            asm volatile("cp.async.commit_group;");
            asm volatile("cp.async.wait_group 1;" ::: "memory");
        } else {
            asm volatile("cp.async.wait_group 0;" ::: "memory");
        }
        __syncthreads();

        const bf16* Ks0 = &KV[s][OFF_KH];
        const bf16* Ks1 = &KV[s][OFF_KL];
        const bf16* Vs0 = &KV[s][OFF_VH];
        const bf16* Vs1 = &KV[s][OFF_VL];

        float sreg[8][4];
        #pragma unroll
        for (int nb = 0; nb < 8; nb++)
            sreg[nb][0] = sreg[nb][1] = sreg[nb][2] = sreg[nb][3] = 0.f;

        #pragma unroll
        for (int c = 0; c < 2; c++) {
            #pragma unroll
            for (int jp = 0; jp < 4; jp++) {
                unsigned kh4[4], kl4[4];
                ldsm4(kh4, &Ks0[(jp * 16 + brow) * QSTR + c * 16 + bcol]);
                ldsm4(kl4, &Ks1[(jp * 16 + brow) * QSTR + c * 16 + bcol]);
                mma16816(sreg[2*jp],   qf[0][c], kh4[0], kh4[1]);
                mma16816(sreg[2*jp],   qf[1][c], kh4[0], kh4[1]);
                mma16816(sreg[2*jp],   qf[0][c], kl4[0], kl4[1]);
                mma16816(sreg[2*jp+1], qf[0][c], kh4[2], kh4[3]);
                mma16816(sreg[2*jp+1], qf[1][c], kh4[2], kh4[3]);
                mma16816(sreg[2*jp+1], qf[0][c], kl4[2], kl4[3]);
            }
        }

        float mx0 = sreg[0][0], mx1 = sreg[0][2];
        #pragma unroll
        for (int nb = 0; nb < 8; nb++) {
            mx0 = fmaxf(mx0, fmaxf(sreg[nb][0], sreg[nb][1]));
            mx1 = fmaxf(mx1, fmaxf(sreg[nb][2], sreg[nb][3]));
        }
        mx0 = fmaxf(mx0, __shfl_xor_sync(~0u, mx0, 1));
        mx0 = fmaxf(mx0, __shfl_xor_sync(~0u, mx0, 2));
        mx1 = fmaxf(mx1, __shfl_xor_sync(~0u, mx1, 1));
        mx1 = fmaxf(mx1, __shfl_xor_sync(~0u, mx1, 2));
        float nm0 = fmaxf(m0r, mx0), nm1 = fmaxf(m1r, mx1);
        float sc0 = __expf(m0r - nm0), sc1 = __expf(m1r - nm1);
        m0r = nm0; m1r = nm1;
        float rs0 = 0.f, rs1 = 0.f;
        #pragma unroll
        for (int nb = 0; nb < 8; nb++) {
            sreg[nb][0] = __expf(sreg[nb][0] - nm0);
            sreg[nb][1] = __expf(sreg[nb][1] - nm0);
            sreg[nb][2] = __expf(sreg[nb][2] - nm1);
            sreg[nb][3] = __expf(sreg[nb][3] - nm1);
            rs0 += sreg[nb][0] + sreg[nb][1];
            rs1 += sreg[nb][2] + sreg[nb][3];
        }
        rs0 += __shfl_xor_sync(~0u, rs0, 1);
        rs0 += __shfl_xor_sync(~0u, rs0, 2);
        rs1 += __shfl_xor_sync(~0u, rs1, 1);
        rs1 += __shfl_xor_sync(~0u, rs1, 2);
        l0 = l0 * sc0 + rs0;  l1 = l1 * sc1 + rs1;
        #pragma unroll
        for (int nb = 0; nb < 4; nb++) {
            oacc[nb][0] *= sc0; oacc[nb][1] *= sc0;
            oacc[nb][2] *= sc1; oacc[nb][3] *= sc1;
        }

        #pragma unroll
        for (int c = 0; c < 4; c++) {
            unsigned pah[4], pal[4];
            #pragma unroll
            for (int r4 = 0; r4 < 4; r4++) {
                int nb = 2 * c + (r4 >> 1);
                int pr = (r4 & 1) * 2;
                float x0 = sreg[nb][pr], x1 = sreg[nb][pr + 1];
                bf16 h0 = __float2bfloat16(x0);
                bf16 h1 = __float2bfloat16(x1);
                bf16 e0b = __float2bfloat16(x0 - __bfloat162float(h0));
                bf16 e1b = __float2bfloat16(x1 - __bfloat162float(h1));
                pah[r4] = pack2(h0, h1);
                pal[r4] = pack2(e0b, e1b);
            }
            #pragma unroll
            for (int np = 0; np < 2; np++) {
                unsigned vh4[4], vl4[4];
                ldsm4(vh4, &Vs0[(np * 16 + brow) * VSTR + c * 16 + bcol]);
                ldsm4(vl4, &Vs1[(np * 16 + brow) * VSTR + c * 16 + bcol]);
                mma16816(oacc[2*np],   pah, vh4[0], vh4[1]);
                mma16816(oacc[2*np],   pal, vh4[0], vh4[1]);
                mma16816(oacc[2*np],   pah, vl4[0], vl4[1]);
                mma16816(oacc[2*np+1], pah, vh4[2], vh4[3]);
                mma16816(oacc[2*np+1], pal, vh4[2], vh4[3]);
                mma16816(oacc[2*np+1], pah, vl4[2], vl4[3]);
            }
        }
        __syncthreads();
    }

    float inv0 = 1.f / l0, inv1 = 1.f / l1;
    int r = lane >> 2;
    int qg = q0 + w * 16 + r;
    size_t ob = (size_t)bh * NQ * HD;
    #pragma unroll
    for (int nb = 0; nb < 4; nb++) {
        int d = nb * 8 + (lane & 3) * 2;
        float2 v0 = make_float2(oacc[nb][0] * inv0, oacc[nb][1] * inv0);
        float2 v1 = make_float2(oacc[nb][2] * inv1, oacc[nb][3] * inv1);
        *(float2*)&O[ob + (size_t)qg * HD + d]       = v0;
        *(float2*)&O[ob + (size_t)(qg + 8) * HD + d] = v1;
    }
}

// ============================== launcher ==================================
extern "C" void kernel_launch(void* const* d_in, const int* in_sizes, int n_in,
                              void* d_out, int out_size)
{
    (void)out_size;
    const float *x=0, *y=0, *wxq=0, *bxq=0, *wyq=0, *byq=0,
                *wpx=0, *bpx=0, *wpy=0, *bpy=0;
    for (int i = 0; i < n_in; i++) {
        const float* p = (const float*)d_in[i];
        switch (in_sizes[i]) {
            case 2097152: x = p;   break;
            case 1048576: y = p;   break;
            case 98304:   wxq = p; break;
            case 196608:  wyq = p; break;
            case 32768:   wpx = p; break;
            case 65536:   wpy = p; break;
            case 256:     bpx = p; break;
            case 512:     bpy = p; break;
            case 384:     if (!bxq) bxq = p; else byq = p; break;
            default: break;
        }
    }
    float* out = (float*)d_out;

    split_w_kernel<<<288, 256>>>(wxq, wyq);
    qkv_mma3_kernel<<<240, 256>>>(x, bxq, y, byq);
    attn_mma_kernel<<<320, 256>>>();
    gemm_proj_kernel<<<768, 256>>>(wpx, bpx, x, wpy, bpy, y, out);
}

// round 9
// speedup vs baseline: 1.0085x; 1.0085x over previous
#include <cuda_runtime.h>
#include <cuda_bf16.h>

#define X_CH   256
#define Y_CH   512
#define DIM    128
#define NHEAD  4
#define HD     32
#define HWX    4096
#define HWY    1024
#define BATCH  2
#define GAMMA  0.17677669529663687f   // 32^-0.5

typedef __nv_bfloat16 bf16;

// ---------------- scratch (device globals; no allocation) ----------------
static __device__ __align__(16) bf16 g_qxh[BATCH*NHEAD*HWX*HD], g_qxl[BATCH*NHEAD*HWX*HD];
static __device__ __align__(16) bf16 g_kxh[BATCH*NHEAD*HWX*HD], g_kxl[BATCH*NHEAD*HWX*HD];
static __device__ __align__(16) bf16 g_vxh[BATCH*NHEAD*HWX*HD], g_vxl[BATCH*NHEAD*HWX*HD];
static __device__ __align__(16) bf16 g_qyh[BATCH*NHEAD*HWY*HD], g_qyl[BATCH*NHEAD*HWY*HD];
static __device__ __align__(16) bf16 g_kyh[BATCH*NHEAD*HWY*HD], g_kyl[BATCH*NHEAD*HWY*HD];
static __device__ __align__(16) bf16 g_vyh[BATCH*NHEAD*HWY*HD], g_vyl[BATCH*NHEAD*HWY*HD];
static __device__ float g_ax[BATCH*NHEAD*HWX*HD];   // attention out [b,h,p,d]
static __device__ float g_ay[BATCH*NHEAD*HWY*HD];
// pre-split QKV weights [M][K] and inputs [B][C][N], bf16 hi/lo
static __device__ __align__(16) bf16 g_wxqh[384*X_CH], g_wxql[384*X_CH];
static __device__ __align__(16) bf16 g_wyqh[384*Y_CH], g_wyql[384*Y_CH];
static __device__ __align__(16) bf16 g_xsh[BATCH*X_CH*HWX], g_xsl[BATCH*X_CH*HWX];
static __device__ __align__(16) bf16 g_ysh[BATCH*Y_CH*HWY], g_ysl[BATCH*Y_CH*HWY];

__device__ __forceinline__ void bsplit(float v, bf16& h, bf16& l) {
    h = __float2bfloat16(v);
    l = __float2bfloat16(v - __bfloat162float(h));
}
__device__ __forceinline__ unsigned pack2(bf16 a, bf16 b) {
    return (unsigned)__bfloat16_as_ushort(a) | ((unsigned)__bfloat16_as_ushort(b) << 16);
}

// ---------------- prep: split QKV weights (validated) ----------------
__global__ void __launch_bounds__(256) split_w_kernel(
    const float* __restrict__ s0, const float* __restrict__ s1)
{
    int e = (blockIdx.x * 256 + threadIdx.x) * 4;
    const float* s; bf16 *dh, *dl;
    if (e < 98304) { s = s0; dh = g_wxqh; dl = g_wxql; }
    else           { e -= 98304; s = s1; dh = g_wyqh; dl = g_wyql; }
    float4 v = *(const float4*)(s + e);
    bf16 h0,l0,h1,l1,h2,l2,h3,l3;
    bsplit(v.x,h0,l0); bsplit(v.y,h1,l1); bsplit(v.z,h2,l2); bsplit(v.w,h3,l3);
    *(uint2*)(dh + e) = make_uint2(pack2(h0,h1), pack2(h2,h3));
    *(uint2*)(dl + e) = make_uint2(pack2(l0,l1), pack2(l2,l3));
}

// ---------------- prep: split inputs elementwise (same layout) ----------
__global__ void __launch_bounds__(256) presplit_x_kernel(
    const float* __restrict__ x, const float* __restrict__ y)
{
    int e = (blockIdx.x * 256 + threadIdx.x) * 4;
    const float* s; bf16 *dh, *dl;
    if (e < BATCH*X_CH*HWX) { s = x; dh = g_xsh; dl = g_xsl; }
    else { e -= BATCH*X_CH*HWX; s = y; dh = g_ysh; dl = g_ysl; }
    float4 v = *(const float4*)(s + e);
    bf16 h0,l0,h1,l1,h2,l2,h3,l3;
    bsplit(v.x,h0,l0); bsplit(v.y,h1,l1); bsplit(v.z,h2,l2); bsplit(v.w,h3,l3);
    *(uint2*)(dh + e) = make_uint2(pack2(h0,h1), pack2(h2,h3));
    *(uint2*)(dl + e) = make_uint2(pack2(l0,l1), pack2(l2,l3));
}

// ---------------- MMA helpers ----------------
__device__ __forceinline__ void ldsm4(unsigned r[4], const void* p) {
    unsigned a = (unsigned)__cvta_generic_to_shared(p);
    asm volatile("ldmatrix.sync.aligned.m8n8.x4.shared.b16 {%0,%1,%2,%3}, [%4];"
        : "=r"(r[0]), "=r"(r[1]), "=r"(r[2]), "=r"(r[3]) : "r"(a));
}
__device__ __forceinline__ void ldsm4t(unsigned r[4], const void* p) {
    unsigned a = (unsigned)__cvta_generic_to_shared(p);
    asm volatile("ldmatrix.sync.aligned.m8n8.x4.trans.shared.b16 {%0,%1,%2,%3}, [%4];"
        : "=r"(r[0]), "=r"(r[1]), "=r"(r[2]), "=r"(r[3]) : "r"(a));
}
__device__ __forceinline__ void mma16816(float c[4], const unsigned a[4],
                                         unsigned b0, unsigned b1) {
    asm volatile("mma.sync.aligned.m16n8k16.row.col.f32.bf16.bf16.f32 "
        "{%0,%1,%2,%3}, {%4,%5,%6,%7}, {%8,%9}, {%0,%1,%2,%3};"
        : "+f"(c[0]), "+f"(c[1]), "+f"(c[2]), "+f"(c[3])
        : "r"(a[0]), "r"(a[1]), "r"(a[2]), "r"(a[3]), "r"(b0), "r"(b1));
}
__device__ __forceinline__ void cpasync16(unsigned dst, const void* src) {
    asm volatile("cp.async.ca.shared.global [%0], [%1], 16;" :: "r"(dst), "l"(src));
}

#define ASTR 24     // A tile [m][16k] row stride (bf16)
#define BSTR 136    // B tile [16k][128n] row stride (bf16), validated
#define ST_A 3072   // A part elems (128*24)
#define ST_B 2176   // B part elems (16*136)
#define ST_TOTAL 10496

// ====== QKV tensor-core GEMM v4: all-bf16, cp.async 2-stage pipeline ======
// blocks [0,48): y (K=512, first); [48,240): x.
__global__ void __launch_bounds__(256) qkv_mma4_kernel(
    const float* __restrict__ bx, const float* __restrict__ by_)
{
    __shared__ __align__(16) char SMB[41984];   // 2 stages * 20992 B
    bf16* SM = (bf16*)SMB;
    float* Cst = (float*)SMB;                   // 32KB fp32, reused post-loop

    const bf16 *Wh, *Wl, *Xh, *Xl;
    const float* bias;
    bf16 *Qh_, *Ql_, *Kh_, *Kl_, *Vh_, *Vl_;
    int N, K, m0, n0, b;
    int blk = blockIdx.x;
    if (blk < 48) {
        N = HWY; K = Y_CH;
        b = blk / 24; int r = blk % 24; m0 = (r % 3) * 128; n0 = (r / 3) * 128;
        Wh = g_wyqh; Wl = g_wyql;
        Xh = g_ysh + (size_t)b * K * N; Xl = g_ysl + (size_t)b * K * N;
        bias = by_;
        Qh_=g_qyh; Ql_=g_qyl; Kh_=g_kyh; Kl_=g_kyl; Vh_=g_vyh; Vl_=g_vyl;
    } else {
        blk -= 48;
        N = HWX; K = X_CH;
        b = blk / 96; int r = blk % 96; m0 = (r % 3) * 128; n0 = (r / 3) * 128;
        Wh = g_wxqh; Wl = g_wxql;
        Xh = g_xsh + (size_t)b * K * N; Xl = g_xsl + (size_t)b * K * N;
        bias = bx;
        Qh_=g_qxh; Ql_=g_qxl; Kh_=g_kxh; Kl_=g_kxl; Vh_=g_vxh; Vl_=g_vxl;
    }

    const int tid = threadIdx.x, lane = tid & 31;
    const int w = tid >> 5;
    const int wm = w & 3, wn = w >> 2;
    const int arow = (lane & 7) + ((lane & 8) ? 8 : 0);
    const int acol = (lane & 16) ? 8 : 0;
    const int bkrow = (lane & 7) + ((lane & 8) ? 8 : 0);
    const int bncol = (lane & 16) ? 8 : 0;

    const unsigned sbase = (unsigned)__cvta_generic_to_shared(SMB);

    // stage-fill: 4 cp.async per thread (2 A-chunks + 2 B-chunks)
    auto fill = [&](int s, int kc) {
        #pragma unroll
        for (int it = 0; it < 2; it++) {
            int id = tid + it * 256;             // 0..511
            int part = id & 1, rid = id >> 1;    // 0..255
            // A: W[m0+row][kc*16 + cc*8 .. +8)
            int row = rid >> 1, cc = rid & 1;
            unsigned adst = sbase + (unsigned)(s*ST_TOTAL + part*ST_A + row*ASTR + cc*8) * 2;
            cpasync16(adst, (part ? Wl : Wh) + (size_t)(m0 + row) * K + kc*16 + cc*8);
            // B: X[kc*16+krow][n0 + nc*8 .. +8)
            int krow = rid >> 4, nc = rid & 15;
            unsigned bdst = sbase + (unsigned)(s*ST_TOTAL + 2*ST_A + part*ST_B + krow*BSTR + nc*8) * 2;
            cpasync16(bdst, (part ? Xl : Xh) + (size_t)(kc*16 + krow) * N + n0 + nc*8);
        }
        asm volatile("cp.async.commit_group;");
    };

    float acc[2][8][4] = {};
    const int nkc = K >> 4;

    fill(0, 0);
    for (int kc = 0; kc < nkc; kc++) {
        const int s = kc & 1;
        if (kc + 1 < nkc) {
            fill(s ^ 1, kc + 1);
            asm volatile("cp.async.wait_group 1;" ::: "memory");
        } else {
            asm volatile("cp.async.wait_group 0;" ::: "memory");
        }
        __syncthreads();

        const bf16* Ah = SM + s*ST_TOTAL;
        const bf16* Al = Ah + ST_A;
        const bf16* Bh = SM + s*ST_TOTAL + 2*ST_A;
        const bf16* Bl = Bh + ST_B;

        unsigned ah[2][4], al[2][4];
        #pragma unroll
        for (int im = 0; im < 2; im++) {
            ldsm4(ah[im], &Ah[(wm*32 + im*16 + arow) * ASTR + acol]);
            ldsm4(al[im], &Al[(wm*32 + im*16 + arow) * ASTR + acol]);
        }
        #pragma unroll
        for (int jn = 0; jn < 4; jn++) {
            unsigned bh4[4], bl4[4];
            const int boff = bkrow * BSTR + wn*64 + jn*16 + bncol;
            ldsm4t(bh4, &Bh[boff]);
            ldsm4t(bl4, &Bl[boff]);
            #pragma unroll
            for (int im = 0; im < 2; im++) {
                mma16816(acc[im][2*jn],   ah[im], bh4[0], bh4[1]);
                mma16816(acc[im][2*jn],   al[im], bh4[0], bh4[1]);
                mma16816(acc[im][2*jn],   ah[im], bl4[0], bl4[1]);
                mma16816(acc[im][2*jn+1], ah[im], bh4[2], bh4[3]);
                mma16816(acc[im][2*jn+1], al[im], bh4[2], bh4[3]);
                mma16816(acc[im][2*jn+1], ah[im], bl4[2], bl4[3]);
            }
        }
        __syncthreads();
    }

    // staged epilogue (validated): fragments -> smem fp32 -> linear scatter
    const int r = lane >> 2, cq = (lane & 3) * 2;
    #pragma unroll
    for (int im = 0; im < 2; im++) {
        __syncthreads();
        #pragma unroll
        for (int j8 = 0; j8 < 8; j8++) {
            int col = wn*64 + j8*8 + cq;
            Cst[(wm*16 + r) * 128 + col]         = acc[im][j8][0];
            Cst[(wm*16 + r) * 128 + col + 1]     = acc[im][j8][1];
            Cst[(wm*16 + r + 8) * 128 + col]     = acc[im][j8][2];
            Cst[(wm*16 + r + 8) * 128 + col + 1] = acc[im][j8][3];
        }
        __syncthreads();
        for (int idx = tid; idx < 64*128; idx += 256) {
            int srow = idx >> 7, scol = idx & 127;
            int o = m0 + (srow >> 4) * 32 + im*16 + (srow & 15);
            int n = n0 + scol;
            float v = Cst[idx] + bias[o];
            int t = o >> 7, h = (o & 127) >> 5, d = o & 31;
            bf16 hh, ll;
            if (t == 0) {
                bsplit(v * GAMMA, hh, ll);
                size_t i2 = ((size_t)(b*NHEAD + h) * N + n) * HD + d;
                Qh_[i2] = hh;  Ql_[i2] = ll;
            } else if (t == 1) {
                bsplit(v, hh, ll);
                size_t i2 = ((size_t)(b*NHEAD + h) * N + n) * HD + d;
                Kh_[i2] = hh;  Kl_[i2] = ll;
            } else {
                bsplit(v, hh, ll);
                size_t i2 = ((size_t)(b*NHEAD + h) * HD + d) * N + n;
                Vh_[i2] = hh;  Vl_[i2] = ll;
            }
        }
    }
}

// ============ merged proj GEMM (fp32, validated round-6) ==================
__global__ void __launch_bounds__(256) gemm_proj_kernel(
    const float* __restrict__ Wx, const float* __restrict__ bpx, const float* __restrict__ Rx,
    const float* __restrict__ Wy, const float* __restrict__ bpy, const float* __restrict__ Ry,
    float* __restrict__ outp)
{
    const float *W, *bias, *Res, *Att;
    float* Out;
    int OC, N, b, m0, n0;
    int blk = blockIdx.x;
    if (blk < 256) {
        OC = Y_CH; N = HWY; W = Wy; bias = bpy; Res = Ry; Att = g_ay;
        Out = outp + (size_t)BATCH * X_CH * HWX;
        b = blk / 128; int r = blk % 128; m0 = (r % 8) * 64; n0 = (r / 8) * 64;
    } else {
        blk -= 256;
        OC = X_CH; N = HWX; W = Wx; bias = bpx; Res = Rx; Att = g_ax;
        Out = outp;
        b = blk / 256; int r = blk % 256; m0 = (r % 4) * 64; n0 = (r / 4) * 64;
    }

    __shared__ __align__(16) float As[16][64];
    __shared__ __align__(16) float Bs[16][64];

    const int tid = threadIdx.x;
    const int ty = tid >> 4, tx = tid & 15;
    const int am = tid >> 2, ak = (tid & 3) << 2;
    const int bn_ = tid >> 2, bkq = (tid & 3) << 2;

    float acc[4][4] = {};

    for (int k0 = 0; k0 < DIM; k0 += 16) {
        float4 av = *(const float4*)(W + (size_t)(m0 + am) * DIM + k0 + ak);
        int c = k0 + bkq;
        int h = c >> 5, d = c & 31;
        float4 bv = *(const float4*)(Att + ((size_t)(b * NHEAD + h) * N + n0 + bn_) * HD + d);
        As[ak+0][am] = av.x; As[ak+1][am] = av.y; As[ak+2][am] = av.z; As[ak+3][am] = av.w;
        Bs[bkq+0][bn_] = bv.x; Bs[bkq+1][bn_] = bv.y; Bs[bkq+2][bn_] = bv.z; Bs[bkq+3][bn_] = bv.w;
        __syncthreads();
        #pragma unroll
        for (int kk = 0; kk < 16; kk++) {
            float4 a4 = *(const float4*)(&As[kk][ty << 2]);
            float4 b4 = *(const float4*)(&Bs[kk][tx << 2]);
            float ar[4] = {a4.x, a4.y, a4.z, a4.w};
            float br[4] = {b4.x, b4.y, b4.z, b4.w};
            #pragma unroll
            for (int i = 0; i < 4; i++)
                #pragma unroll
                for (int j = 0; j < 4; j++)
                    acc[i][j] += ar[i] * br[j];
        }
        __syncthreads();
    }

    #pragma unroll
    for (int i = 0; i < 4; i++) {
        int o = m0 + (ty << 2) + i;
        float bval = bias[o];
        size_t off = ((size_t)b * OC + o) * N + n0 + (tx << 2);
        float4 rr = *(const float4*)(Res + off);
        float4 v;
        v.x = acc[i][0] + bval + rr.x;
        v.y = acc[i][1] + bval + rr.y;
        v.z = acc[i][2] + bval + rr.z;
        v.w = acc[i][3] + bval + rr.w;
        *(float4*)(Out + off) = v;
    }
}

// ====== MMA flash attention (round-7 validated: 4 warps, cp.async) ========
#define QSTR 40
#define VSTR 72
#define OFF_KH 0
#define OFF_KL 2560
#define OFF_VH 5120
#define OFF_VL 7424
#define STAGE_ELEMS 9728

__global__ void __launch_bounds__(128) attn_mma_kernel()
{
    __shared__ __align__(16) bf16 KV[2][STAGE_ELEMS];

    int blk = blockIdx.x;
    const bf16 *Qh, *Ql, *Kh, *Kl, *Vh, *Vl; float* O;
    int NQ, NK, bh, q0;
    if (blk < 128) {   // dir1: y attends x
        bh = blk >> 4; q0 = (blk & 15) * 64; NQ = HWY; NK = HWX;
        Qh=g_qyh; Ql=g_qyl; Kh=g_kxh; Kl=g_kxl; Vh=g_vxh; Vl=g_vxl; O=g_ay;
    } else {           // dir0: x attends y
        blk -= 128;
        bh = blk >> 6; q0 = (blk & 63) * 64; NQ = HWX; NK = HWY;
        Qh=g_qxh; Ql=g_qxl; Kh=g_kyh; Kl=g_kyl; Vh=g_vyh; Vl=g_vyl; O=g_ax;
    }

    const int tid = threadIdx.x, w = tid >> 5, lane = tid & 31;
    const size_t kbase = (size_t)bh * NK * HD;
    const size_t vbase = (size_t)bh * HD * NK;
    const int nt = NK >> 6;

    const int e0 = tid * 8, e1 = (tid + 128) * 8;
    const int ks0 = (e0 >> 5) * QSTR + (e0 & 31);
    const int ks1 = (e1 >> 5) * QSTR + (e1 & 31);
    const int vs0 = (e0 >> 6) * VSTR + (e0 & 63);
    const int vs1 = (e1 >> 6) * VSTR + (e1 & 63);
    const size_t kg0 = (size_t)(e0 >> 5) * HD + (e0 & 31);
    const size_t kg1 = (size_t)(e1 >> 5) * HD + (e1 & 31);
    const size_t vg0 = (size_t)(e0 >> 6) * NK + (e0 & 63);
    const size_t vg1 = (size_t)(e1 >> 6) * NK + (e1 & 63);

    unsigned sb0 = (unsigned)__cvta_generic_to_shared(&KV[0][0]);
    unsigned sb1 = (unsigned)__cvta_generic_to_shared(&KV[1][0]);

    {
        size_t ka = kbase, va = vbase;
        cpasync16(sb0 + (OFF_KH + ks0) * 2, Kh + ka + kg0);
        cpasync16(sb0 + (OFF_KH + ks1) * 2, Kh + ka + kg1);
        cpasync16(sb0 + (OFF_KL + ks0) * 2, Kl + ka + kg0);
        cpasync16(sb0 + (OFF_KL + ks1) * 2, Kl + ka + kg1);
        cpasync16(sb0 + (OFF_VH + vs0) * 2, Vh + va + vg0);
        cpasync16(sb0 + (OFF_VH + vs1) * 2, Vh + va + vg1);
        cpasync16(sb0 + (OFF_VL + vs0) * 2, Vl + va + vg0);
        cpasync16(sb0 + (OFF_VL + vs1) * 2, Vl + va + vg1);
        asm volatile("cp.async.commit_group;");
    }

    {
        bf16* Qsh = &KV[1][0];
        bf16* Qsl = &KV[1][2560];
        const size_t qb = (size_t)bh * NQ * HD + (size_t)q0 * HD;
        #pragma unroll
        for (int it = 0; it < 2; it++) {
            int e = (tid + it * 128) * 8;
            int row = e >> 5, col = e & 31;
            *(uint4*)&Qsh[row * QSTR + col] = *(const uint4*)(Qh + qb + (size_t)row * HD + col);
            *(uint4*)&Qsl[row * QSTR + col] = *(const uint4*)(Ql + qb + (size_t)row * HD + col);
        }
    }
    __syncthreads();

    const int arow = (lane & 7) + ((lane & 8) ? 8 : 0);
    const int acol = (lane & 16) ? 8 : 0;
    const int brow = (lane & 7) + ((lane & 16) ? 8 : 0);
    const int bcol = (lane & 8) ? 8 : 0;
    unsigned qf[2][2][4];
    #pragma unroll
    for (int p = 0; p < 2; p++)
        #pragma unroll
        for (int c = 0; c < 2; c++)
            ldsm4(qf[p][c], &KV[1][p * 2560 + (w * 16 + arow) * QSTR + c * 16 + acol]);
    __syncthreads();

    float m0r = -1e30f, m1r = -1e30f, l0 = 0.f, l1 = 0.f;
    float oacc[4][4] = {};

    for (int kt = 0; kt < nt; kt++) {
        const int s = kt & 1;
        if (kt + 1 < nt) {
            unsigned sb = (s ^ 1) ? sb1 : sb0;
            size_t ka = kbase + (size_t)(kt + 1) * 64 * HD;
            size_t va = vbase + (size_t)(kt + 1) * 64;
            cpasync16(sb + (OFF_KH + ks0) * 2, Kh + ka + kg0);
            cpasync16(sb + (OFF_KH + ks1) * 2, Kh + ka + kg1);
            cpasync16(sb + (OFF_KL + ks0) * 2, Kl + ka + kg0);
            cpasync16(sb + (OFF_KL + ks1) * 2, Kl + ka + kg1);
            cpasync16(sb + (OFF_VH + vs0) * 2, Vh + va + vg0);
            cpasync16(sb + (OFF_VH + vs1) * 2, Vh + va + vg1);
            cpasync16(sb + (OFF_VL + vs0) * 2, Vl + va + vg0);
            cpasync16(sb + (OFF_VL + vs1) * 2, Vl + va + vg1);
            asm volatile("cp.async.commit_group;");
            asm volatile("cp.async.wait_group 1;" ::: "memory");
        } else {
            asm volatile("cp.async.wait_group 0;" ::: "memory");
        }
        __syncthreads();

        const bf16* Ks0 = &KV[s][OFF_KH];
        const bf16* Ks1 = &KV[s][OFF_KL];
        const bf16* Vs0 = &KV[s][OFF_VH];
        const bf16* Vs1 = &KV[s][OFF_VL];

        float sreg[8][4];
        #pragma unroll
        for (int nb = 0; nb < 8; nb++)
            sreg[nb][0] = sreg[nb][1] = sreg[nb][2] = sreg[nb][3] = 0.f;

        #pragma unroll
        for (int c = 0; c < 2; c++) {
            #pragma unroll
            for (int jp = 0; jp < 4; jp++) {
                unsigned kh4[4], kl4[4];
                ldsm4(kh4, &Ks0[(jp * 16 + brow) * QSTR + c * 16 + bcol]);
                ldsm4(kl4, &Ks1[(jp * 16 + brow) * QSTR + c * 16 + bcol]);
                mma16816(sreg[2*jp],   qf[0][c], kh4[0], kh4[1]);
                mma16816(sreg[2*jp],   qf[1][c], kh4[0], kh4[1]);
                mma16816(sreg[2*jp],   qf[0][c], kl4[0], kl4[1]);
                mma16816(sreg[2*jp+1], qf[0][c], kh4[2], kh4[3]);
                mma16816(sreg[2*jp+1], qf[1][c], kh4[2], kh4[3]);
                mma16816(sreg[2*jp+1], qf[0][c], kl4[2], kl4[3]);
            }
        }

        float mx0 = sreg[0][0], mx1 = sreg[0][2];
        #pragma unroll
        for (int nb = 0; nb < 8; nb++) {
            mx0 = fmaxf(mx0, fmaxf(sreg[nb][0], sreg[nb][1]));
            mx1 = fmaxf(mx1, fmaxf(sreg[nb][2], sreg[nb][3]));
        }
        mx0 = fmaxf(mx0, __shfl_xor_sync(~0u, mx0, 1));
        mx0 = fmaxf(mx0, __shfl_xor_sync(~0u, mx0, 2));
        mx1 = fmaxf(mx1, __shfl_xor_sync(~0u, mx1, 1));
        mx1 = fmaxf(mx1, __shfl_xor_sync(~0u, mx1, 2));
        float nm0 = fmaxf(m0r, mx0), nm1 = fmaxf(m1r, mx1);
        float sc0 = __expf(m0r - nm0), sc1 = __expf(m1r - nm1);
        m0r = nm0; m1r = nm1;
        float rs0 = 0.f, rs1 = 0.f;
        #pragma unroll
        for (int nb = 0; nb < 8; nb++) {
            sreg[nb][0] = __expf(sreg[nb][0] - nm0);
            sreg[nb][1] = __expf(sreg[nb][1] - nm0);
            sreg[nb][2] = __expf(sreg[nb][2] - nm1);
            sreg[nb][3] = __expf(sreg[nb][3] - nm1);
            rs0 += sreg[nb][0] + sreg[nb][1];
            rs1 += sreg[nb][2] + sreg[nb][3];
        }
        rs0 += __shfl_xor_sync(~0u, rs0, 1);
        rs0 += __shfl_xor_sync(~0u, rs0, 2);
        rs1 += __shfl_xor_sync(~0u, rs1, 1);
        rs1 += __shfl_xor_sync(~0u, rs1, 2);
        l0 = l0 * sc0 + rs0;  l1 = l1 * sc1 + rs1;
        #pragma unroll
        for (int nb = 0; nb < 4; nb++) {
            oacc[nb][0] *= sc0; oacc[nb][1] *= sc0;
            oacc[nb][2] *= sc1; oacc[nb][3] *= sc1;
        }

        #pragma unroll
        for (int c = 0; c < 4; c++) {
            unsigned pah[4], pal[4];
            #pragma unroll
            for (int r4 = 0; r4 < 4; r4++) {
                int nb = 2 * c + (r4 >> 1);
                int pr = (r4 & 1) * 2;
                float x0 = sreg[nb][pr], x1 = sreg[nb][pr + 1];
                bf16 h0 = __float2bfloat16(x0);
                bf16 h1 = __float2bfloat16(x1);
                bf16 e0b = __float2bfloat16(x0 - __bfloat162float(h0));
                bf16 e1b = __float2bfloat16(x1 - __bfloat162float(h1));
                pah[r4] = pack2(h0, h1);
                pal[r4] = pack2(e0b, e1b);
            }
            #pragma unroll
            for (int np = 0; np < 2; np++) {
                unsigned vh4[4], vl4[4];
                ldsm4(vh4, &Vs0[(np * 16 + brow) * VSTR + c * 16 + bcol]);
                ldsm4(vl4, &Vs1[(np * 16 + brow) * VSTR + c * 16 + bcol]);
                mma16816(oacc[2*np],   pah, vh4[0], vh4[1]);
                mma16816(oacc[2*np],   pal, vh4[0], vh4[1]);
                mma16816(oacc[2*np],   pah, vl4[0], vl4[1]);
                mma16816(oacc[2*np+1], pah, vh4[2], vh4[3]);
                mma16816(oacc[2*np+1], pal, vh4[2], vh4[3]);
                mma16816(oacc[2*np+1], pah, vl4[2], vl4[3]);
            }
        }
        __syncthreads();
    }

    float inv0 = 1.f / l0, inv1 = 1.f / l1;
    int r = lane >> 2;
    int qg = q0 + w * 16 + r;
    size_t ob = (size_t)bh * NQ * HD;
    #pragma unroll
    for (int nb = 0; nb < 4; nb++) {
        int d = nb * 8 + (lane & 3) * 2;
        float2 v0 = make_float2(oacc[nb][0] * inv0, oacc[nb][1] * inv0);
        float2 v1 = make_float2(oacc[nb][2] * inv1, oacc[nb][3] * inv1);
        *(float2*)&O[ob + (size_t)qg * HD + d]       = v0;
        *(float2*)&O[ob + (size_t)(qg + 8) * HD + d] = v1;
    }
}

// ============================== launcher ==================================
extern "C" void kernel_launch(void* const* d_in, const int* in_sizes, int n_in,
                              void* d_out, int out_size)
{
    (void)out_size;
    const float *x=0, *y=0, *wxq=0, *bxq=0, *wyq=0, *byq=0,
                *wpx=0, *bpx=0, *wpy=0, *bpy=0;
    for (int i = 0; i < n_in; i++) {
        const float* p = (const float*)d_in[i];
        switch (in_sizes[i]) {
            case 2097152: x = p;   break;
            case 1048576: y = p;   break;
            case 98304:   wxq = p; break;
            case 196608:  wyq = p; break;
            case 32768:   wpx = p; break;
            case 65536:   wpy = p; break;
            case 256:     bpx = p; break;
            case 512:     bpy = p; break;
            case 384:     if (!bxq) bxq = p; else byq = p; break;
            default: break;
        }
    }
    float* out = (float*)d_out;

    split_w_kernel<<<288, 256>>>(wxq, wyq);
    presplit_x_kernel<<<3072, 256>>>(x, y);
    qkv_mma4_kernel<<<240, 256>>>(bxq, byq);
    attn_mma_kernel<<<640, 128>>>();
    gemm_proj_kernel<<<768, 256>>>(wpx, bpx, x, wpy, bpy, y, out);
}

// round 10
// speedup vs baseline: 1.1214x; 1.1119x over previous
#include <cuda_runtime.h>
#include <cuda_bf16.h>

#define X_CH   256
#define Y_CH   512
#define DIM    128
#define NHEAD  4
#define HD     32
#define HWX    4096
#define HWY    1024
#define BATCH  2
#define GAMMA  0.17677669529663687f   // 32^-0.5
// Q pre-scale: GAMMA * log2(e), so softmax can use exp2
#define GAMMA_L2E (0.17677669529663687f * 1.4426950408889634f)

typedef __nv_bfloat16 bf16;

// ---------------- scratch (device globals; no allocation) ----------------
static __device__ __align__(16) bf16 g_qxh[BATCH*NHEAD*HWX*HD], g_qxl[BATCH*NHEAD*HWX*HD];
static __device__ __align__(16) bf16 g_kxh[BATCH*NHEAD*HWX*HD], g_kxl[BATCH*NHEAD*HWX*HD];
static __device__ __align__(16) bf16 g_vxh[BATCH*NHEAD*HWX*HD], g_vxl[BATCH*NHEAD*HWX*HD];
static __device__ __align__(16) bf16 g_qyh[BATCH*NHEAD*HWY*HD], g_qyl[BATCH*NHEAD*HWY*HD];
static __device__ __align__(16) bf16 g_kyh[BATCH*NHEAD*HWY*HD], g_kyl[BATCH*NHEAD*HWY*HD];
static __device__ __align__(16) bf16 g_vyh[BATCH*NHEAD*HWY*HD], g_vyl[BATCH*NHEAD*HWY*HD];
static __device__ float g_ax[BATCH*NHEAD*HWX*HD];   // attention out [b,h,p,d]
static __device__ float g_ay[BATCH*NHEAD*HWY*HD];
// pre-split QKV weights [M][K] and inputs [B][C][N], bf16 hi/lo
static __device__ __align__(16) bf16 g_wxqh[384*X_CH], g_wxql[384*X_CH];
static __device__ __align__(16) bf16 g_wyqh[384*Y_CH], g_wyql[384*Y_CH];
static __device__ __align__(16) bf16 g_xsh[BATCH*X_CH*HWX], g_xsl[BATCH*X_CH*HWX];
static __device__ __align__(16) bf16 g_ysh[BATCH*Y_CH*HWY], g_ysl[BATCH*Y_CH*HWY];

__device__ __forceinline__ void bsplit(float v, bf16& h, bf16& l) {
    h = __float2bfloat16(v);
    l = __float2bfloat16(v - __bfloat162float(h));
}
__device__ __forceinline__ unsigned pack2(bf16 a, bf16 b) {
    return (unsigned)__bfloat16_as_ushort(a) | ((unsigned)__bfloat16_as_ushort(b) << 16);
}
// packed split: {x0,x1} -> hi bf16x2 (lo half = x0) + residual bf16x2
__device__ __forceinline__ void psplit2(float x0, float x1, unsigned& ph, unsigned& pl) {
    unsigned h;
    asm("cvt.rn.bf16x2.f32 %0, %1, %2;" : "=r"(h) : "f"(x1), "f"(x0));
    float h0 = __uint_as_float(h << 16);
    float h1 = __uint_as_float(h & 0xffff0000u);
    float e0 = x0 - h0, e1 = x1 - h1;
    asm("cvt.rn.bf16x2.f32 %0, %1, %2;" : "=r"(pl) : "f"(e1), "f"(e0));
    ph = h;
}

// ---------------- prep: split QKV weights (validated) ----------------
__global__ void __launch_bounds__(256) split_w_kernel(
    const float* __restrict__ s0, const float* __restrict__ s1)
{
    int e = (blockIdx.x * 256 + threadIdx.x) * 4;
    const float* s; bf16 *dh, *dl;
    if (e < 98304) { s = s0; dh = g_wxqh; dl = g_wxql; }
    else           { e -= 98304; s = s1; dh = g_wyqh; dl = g_wyql; }
    float4 v = *(const float4*)(s + e);
    bf16 h0,l0,h1,l1,h2,l2,h3,l3;
    bsplit(v.x,h0,l0); bsplit(v.y,h1,l1); bsplit(v.z,h2,l2); bsplit(v.w,h3,l3);
    *(uint2*)(dh + e) = make_uint2(pack2(h0,h1), pack2(h2,h3));
    *(uint2*)(dl + e) = make_uint2(pack2(l0,l1), pack2(l2,l3));
}

// ---------------- prep: split inputs elementwise (validated) ----------
__global__ void __launch_bounds__(256) presplit_x_kernel(
    const float* __restrict__ x, const float* __restrict__ y)
{
    int e = (blockIdx.x * 256 + threadIdx.x) * 4;
    const float* s; bf16 *dh, *dl;
    if (e < BATCH*X_CH*HWX) { s = x; dh = g_xsh; dl = g_xsl; }
    else { e -= BATCH*X_CH*HWX; s = y; dh = g_ysh; dl = g_ysl; }
    float4 v = *(const float4*)(s + e);
    bf16 h0,l0,h1,l1,h2,l2,h3,l3;
    bsplit(v.x,h0,l0); bsplit(v.y,h1,l1); bsplit(v.z,h2,l2); bsplit(v.w,h3,l3);
    *(uint2*)(dh + e) = make_uint2(pack2(h0,h1), pack2(h2,h3));
    *(uint2*)(dl + e) = make_uint2(pack2(l0,l1), pack2(l2,l3));
}

// ---------------- MMA helpers ----------------
__device__ __forceinline__ void ldsm4(unsigned r[4], const void* p) {
    unsigned a = (unsigned)__cvta_generic_to_shared(p);
    asm volatile("ldmatrix.sync.aligned.m8n8.x4.shared.b16 {%0,%1,%2,%3}, [%4];"
        : "=r"(r[0]), "=r"(r[1]), "=r"(r[2]), "=r"(r[3]) : "r"(a));
}
__device__ __forceinline__ void ldsm4t(unsigned r[4], const void* p) {
    unsigned a = (unsigned)__cvta_generic_to_shared(p);
    asm volatile("ldmatrix.sync.aligned.m8n8.x4.trans.shared.b16 {%0,%1,%2,%3}, [%4];"
        : "=r"(r[0]), "=r"(r[1]), "=r"(r[2]), "=r"(r[3]) : "r"(a));
}
__device__ __forceinline__ void mma16816(float c[4], const unsigned a[4],
                                         unsigned b0, unsigned b1) {
    asm volatile("mma.sync.aligned.m16n8k16.row.col.f32.bf16.bf16.f32 "
        "{%0,%1,%2,%3}, {%4,%5,%6,%7}, {%8,%9}, {%0,%1,%2,%3};"
        : "+f"(c[0]), "+f"(c[1]), "+f"(c[2]), "+f"(c[3])
        : "r"(a[0]), "r"(a[1]), "r"(a[2]), "r"(a[3]), "r"(b0), "r"(b1));
}
__device__ __forceinline__ void cpasync16(unsigned dst, const void* src) {
    asm volatile("cp.async.ca.shared.global [%0], [%1], 16;" :: "r"(dst), "l"(src));
}

#define ASTR 24     // A tile [m][16k] row stride (bf16)
#define BSTR 136    // B tile [16k][128n] row stride (bf16)
#define ST_A 3072   // A part elems (128*24)
#define ST_B 2176   // B part elems (16*136)
#define ST_TOTAL 10496

// ====== QKV tensor-core GEMM v4 (validated round-9) =======================
// blocks [0,48): y (K=512, first); [48,240): x.
__global__ void __launch_bounds__(256) qkv_mma4_kernel(
    const float* __restrict__ bx, const float* __restrict__ by_)
{
    __shared__ __align__(16) char SMB[41984];
    bf16* SM = (bf16*)SMB;
    float* Cst = (float*)SMB;

    const bf16 *Wh, *Wl, *Xh, *Xl;
    const float* bias;
    bf16 *Qh_, *Ql_, *Kh_, *Kl_, *Vh_, *Vl_;
    int N, K, m0, n0, b;
    int blk = blockIdx.x;
    if (blk < 48) {
        N = HWY; K = Y_CH;
        b = blk / 24; int r = blk % 24; m0 = (r % 3) * 128; n0 = (r / 3) * 128;
        Wh = g_wyqh; Wl = g_wyql;
        Xh = g_ysh + (size_t)b * K * N; Xl = g_ysl + (size_t)b * K * N;
        bias = by_;
        Qh_=g_qyh; Ql_=g_qyl; Kh_=g_kyh; Kl_=g_kyl; Vh_=g_vyh; Vl_=g_vyl;
    } else {
        blk -= 48;
        N = HWX; K = X_CH;
        b = blk / 96; int r = blk % 96; m0 = (r % 3) * 128; n0 = (r / 3) * 128;
        Wh = g_wxqh; Wl = g_wxql;
        Xh = g_xsh + (size_t)b * K * N; Xl = g_xsl + (size_t)b * K * N;
        bias = bx;
        Qh_=g_qxh; Ql_=g_qxl; Kh_=g_kxh; Kl_=g_kxl; Vh_=g_vxh; Vl_=g_vxl;
    }

    const int tid = threadIdx.x, lane = tid & 31;
    const int w = tid >> 5;
    const int wm = w & 3, wn = w >> 2;
    const int arow = (lane & 7) + ((lane & 8) ? 8 : 0);
    const int acol = (lane & 16) ? 8 : 0;
    const int bkrow = (lane & 7) + ((lane & 8) ? 8 : 0);
    const int bncol = (lane & 16) ? 8 : 0;

    const unsigned sbase = (unsigned)__cvta_generic_to_shared(SMB);

    auto fill = [&](int s, int kc) {
        #pragma unroll
        for (int it = 0; it < 2; it++) {
            int id = tid + it * 256;
            int part = id & 1, rid = id >> 1;
            int row = rid >> 1, cc = rid & 1;
            unsigned adst = sbase + (unsigned)(s*ST_TOTAL + part*ST_A + row*ASTR + cc*8) * 2;
            cpasync16(adst, (part ? Wl : Wh) + (size_t)(m0 + row) * K + kc*16 + cc*8);
            int krow = rid >> 4, nc = rid & 15;
            unsigned bdst = sbase + (unsigned)(s*ST_TOTAL + 2*ST_A + part*ST_B + krow*BSTR + nc*8) * 2;
            cpasync16(bdst, (part ? Xl : Xh) + (size_t)(kc*16 + krow) * N + n0 + nc*8);
        }
        asm volatile("cp.async.commit_group;");
    };

    float acc[2][8][4] = {};
    const int nkc = K >> 4;

    fill(0, 0);
    for (int kc = 0; kc < nkc; kc++) {
        const int s = kc & 1;
        if (kc + 1 < nkc) {
            fill(s ^ 1, kc + 1);
            asm volatile("cp.async.wait_group 1;" ::: "memory");
        } else {
            asm volatile("cp.async.wait_group 0;" ::: "memory");
        }
        __syncthreads();

        const bf16* Ah = SM + s*ST_TOTAL;
        const bf16* Al = Ah + ST_A;
        const bf16* Bh = SM + s*ST_TOTAL + 2*ST_A;
        const bf16* Bl = Bh + ST_B;

        unsigned ah[2][4], al[2][4];
        #pragma unroll
        for (int im = 0; im < 2; im++) {
            ldsm4(ah[im], &Ah[(wm*32 + im*16 + arow) * ASTR + acol]);
            ldsm4(al[im], &Al[(wm*32 + im*16 + arow) * ASTR + acol]);
        }
        #pragma unroll
        for (int jn = 0; jn < 4; jn++) {
            unsigned bh4[4], bl4[4];
            const int boff = bkrow * BSTR + wn*64 + jn*16 + bncol;
            ldsm4t(bh4, &Bh[boff]);
            ldsm4t(bl4, &Bl[boff]);
            #pragma unroll
            for (int im = 0; im < 2; im++) {
                mma16816(acc[im][2*jn],   ah[im], bh4[0], bh4[1]);
                mma16816(acc[im][2*jn],   al[im], bh4[0], bh4[1]);
                mma16816(acc[im][2*jn],   ah[im], bl4[0], bl4[1]);
                mma16816(acc[im][2*jn+1], ah[im], bh4[2], bh4[3]);
                mma16816(acc[im][2*jn+1], al[im], bh4[2], bh4[3]);
                mma16816(acc[im][2*jn+1], ah[im], bl4[2], bl4[3]);
            }
        }
        __syncthreads();
    }

    // staged epilogue (validated). Q scaled by GAMMA*log2(e) for exp2 softmax.
    const int r = lane >> 2, cq = (lane & 3) * 2;
    #pragma unroll
    for (int im = 0; im < 2; im++) {
        __syncthreads();
        #pragma unroll
        for (int j8 = 0; j8 < 8; j8++) {
            int col = wn*64 + j8*8 + cq;
            Cst[(wm*16 + r) * 128 + col]         = acc[im][j8][0];
            Cst[(wm*16 + r) * 128 + col + 1]     = acc[im][j8][1];
            Cst[(wm*16 + r + 8) * 128 + col]     = acc[im][j8][2];
            Cst[(wm*16 + r + 8) * 128 + col + 1] = acc[im][j8][3];
        }
        __syncthreads();
        for (int idx = tid; idx < 64*128; idx += 256) {
            int srow = idx >> 7, scol = idx & 127;
            int o = m0 + (srow >> 4) * 32 + im*16 + (srow & 15);
            int n = n0 + scol;
            float v = Cst[idx] + bias[o];
            int t = o >> 7, h = (o & 127) >> 5, d = o & 31;
            bf16 hh, ll;
            if (t == 0) {
                bsplit(v * GAMMA_L2E, hh, ll);
                size_t i2 = ((size_t)(b*NHEAD + h) * N + n) * HD + d;
                Qh_[i2] = hh;  Ql_[i2] = ll;
            } else if (t == 1) {
                bsplit(v, hh, ll);
                size_t i2 = ((size_t)(b*NHEAD + h) * N + n) * HD + d;
                Kh_[i2] = hh;  Kl_[i2] = ll;
            } else {
                bsplit(v, hh, ll);
                size_t i2 = ((size_t)(b*NHEAD + h) * HD + d) * N + n;
                Vh_[i2] = hh;  Vl_[i2] = ll;
            }
        }
    }
}

// ============ merged proj GEMM (fp32, validated round-6) ==================
__global__ void __launch_bounds__(256) gemm_proj_kernel(
    const float* __restrict__ Wx, const float* __restrict__ bpx, const float* __restrict__ Rx,
    const float* __restrict__ Wy, const float* __restrict__ bpy, const float* __restrict__ Ry,
    float* __restrict__ outp)
{
    const float *W, *bias, *Res, *Att;
    float* Out;
    int OC, N, b, m0, n0;
    int blk = blockIdx.x;
    if (blk < 256) {
        OC = Y_CH; N = HWY; W = Wy; bias = bpy; Res = Ry; Att = g_ay;
        Out = outp + (size_t)BATCH * X_CH * HWX;
        b = blk / 128; int r = blk % 128; m0 = (r % 8) * 64; n0 = (r / 8) * 64;
    } else {
        blk -= 256;
        OC = X_CH; N = HWX; W = Wx; bias = bpx; Res = Rx; Att = g_ax;
        Out = outp;
        b = blk / 256; int r = blk % 256; m0 = (r % 4) * 64; n0 = (r / 4) * 64;
    }

    __shared__ __align__(16) float As[16][64];
    __shared__ __align__(16) float Bs[16][64];

    const int tid = threadIdx.x;
    const int ty = tid >> 4, tx = tid & 15;
    const int am = tid >> 2, ak = (tid & 3) << 2;
    const int bn_ = tid >> 2, bkq = (tid & 3) << 2;

    float acc[4][4] = {};

    for (int k0 = 0; k0 < DIM; k0 += 16) {
        float4 av = *(const float4*)(W + (size_t)(m0 + am) * DIM + k0 + ak);
        int c = k0 + bkq;
        int h = c >> 5, d = c & 31;
        float4 bv = *(const float4*)(Att + ((size_t)(b * NHEAD + h) * N + n0 + bn_) * HD + d);
        As[ak+0][am] = av.x; As[ak+1][am] = av.y; As[ak+2][am] = av.z; As[ak+3][am] = av.w;
        Bs[bkq+0][bn_] = bv.x; Bs[bkq+1][bn_] = bv.y; Bs[bkq+2][bn_] = bv.z; Bs[bkq+3][bn_] = bv.w;
        __syncthreads();
        #pragma unroll
        for (int kk = 0; kk < 16; kk++) {
            float4 a4 = *(const float4*)(&As[kk][ty << 2]);
            float4 b4 = *(const float4*)(&Bs[kk][tx << 2]);
            float ar[4] = {a4.x, a4.y, a4.z, a4.w};
            float br[4] = {b4.x, b4.y, b4.z, b4.w};
            #pragma unroll
            for (int i = 0; i < 4; i++)
                #pragma unroll
                for (int j = 0; j < 4; j++)
                    acc[i][j] += ar[i] * br[j];
        }
        __syncthreads();
    }

    #pragma unroll
    for (int i = 0; i < 4; i++) {
        int o = m0 + (ty << 2) + i;
        float bval = bias[o];
        size_t off = ((size_t)b * OC + o) * N + n0 + (tx << 2);
        float4 rr = *(const float4*)(Res + off);
        float4 v;
        v.x = acc[i][0] + bval + rr.x;
        v.y = acc[i][1] + bval + rr.y;
        v.z = acc[i][2] + bval + rr.z;
        v.w = acc[i][3] + bval + rr.w;
        *(float4*)(Out + off) = v;
    }
}

// ====== MMA flash attention: exp2 softmax + packed P-split ================
#define QSTR 40
#define VSTR 72
#define OFF_KH 0
#define OFF_KL 2560
#define OFF_VH 5120
#define OFF_VL 7424
#define STAGE_ELEMS 9728

__global__ void __launch_bounds__(128) attn_mma_kernel()
{
    __shared__ __align__(16) bf16 KV[2][STAGE_ELEMS];

    int blk = blockIdx.x;
    const bf16 *Qh, *Ql, *Kh, *Kl, *Vh, *Vl; float* O;
    int NQ, NK, bh, q0;
    if (blk < 128) {   // dir1: y attends x
        bh = blk >> 4; q0 = (blk & 15) * 64; NQ = HWY; NK = HWX;
        Qh=g_qyh; Ql=g_qyl; Kh=g_kxh; Kl=g_kxl; Vh=g_vxh; Vl=g_vxl; O=g_ay;
    } else {           // dir0: x attends y
        blk -= 128;
        bh = blk >> 6; q0 = (blk & 63) * 64; NQ = HWX; NK = HWY;
        Qh=g_qxh; Ql=g_qxl; Kh=g_kyh; Kl=g_kyl; Vh=g_vyh; Vl=g_vyl; O=g_ax;
    }

    const int tid = threadIdx.x, w = tid >> 5, lane = tid & 31;
    const size_t kbase = (size_t)bh * NK * HD;
    const size_t vbase = (size_t)bh * HD * NK;
    const int nt = NK >> 6;

    const int e0 = tid * 8, e1 = (tid + 128) * 8;
    const int ks0 = (e0 >> 5) * QSTR + (e0 & 31);
    const int ks1 = (e1 >> 5) * QSTR + (e1 & 31);
    const int vs0 = (e0 >> 6) * VSTR + (e0 & 63);
    const int vs1 = (e1 >> 6) * VSTR + (e1 & 63);
    const size_t kg0 = (size_t)(e0 >> 5) * HD + (e0 & 31);
    const size_t kg1 = (size_t)(e1 >> 5) * HD + (e1 & 31);
    const size_t vg0 = (size_t)(e0 >> 6) * NK + (e0 & 63);
    const size_t vg1 = (size_t)(e1 >> 6) * NK + (e1 & 63);

    unsigned sb0 = (unsigned)__cvta_generic_to_shared(&KV[0][0]);
    unsigned sb1 = (unsigned)__cvta_generic_to_shared(&KV[1][0]);

    {
        size_t ka = kbase, va = vbase;
        cpasync16(sb0 + (OFF_KH + ks0) * 2, Kh + ka + kg0);
        cpasync16(sb0 + (OFF_KH + ks1) * 2, Kh + ka + kg1);
        cpasync16(sb0 + (OFF_KL + ks0) * 2, Kl + ka + kg0);
        cpasync16(sb0 + (OFF_KL + ks1) * 2, Kl + ka + kg1);
        cpasync16(sb0 + (OFF_VH + vs0) * 2, Vh + va + vg0);
        cpasync16(sb0 + (OFF_VH + vs1) * 2, Vh + va + vg1);
        cpasync16(sb0 + (OFF_VL + vs0) * 2, Vl + va + vg0);
        cpasync16(sb0 + (OFF_VL + vs1) * 2, Vl + va + vg1);
        asm volatile("cp.async.commit_group;");
    }

    {
        bf16* Qsh = &KV[1][0];
        bf16* Qsl = &KV[1][2560];
        const size_t qb = (size_t)bh * NQ * HD + (size_t)q0 * HD;
        #pragma unroll
        for (int it = 0; it < 2; it++) {
            int e = (tid + it * 128) * 8;
            int row = e >> 5, col = e & 31;
            *(uint4*)&Qsh[row * QSTR + col] = *(const uint4*)(Qh + qb + (size_t)row * HD + col);
            *(uint4*)&Qsl[row * QSTR + col] = *(const uint4*)(Ql + qb + (size_t)row * HD + col);
        }
    }
    __syncthreads();

    const int arow = (lane & 7) + ((lane & 8) ? 8 : 0);
    const int acol = (lane & 16) ? 8 : 0;
    const int brow = (lane & 7) + ((lane & 16) ? 8 : 0);
    const int bcol = (lane & 8) ? 8 : 0;
    unsigned qf[2][2][4];
    #pragma unroll
    for (int p = 0; p < 2; p++)
        #pragma unroll
        for (int c = 0; c < 2; c++)
            ldsm4(qf[p][c], &KV[1][p * 2560 + (w * 16 + arow) * QSTR + c * 16 + acol]);
    __syncthreads();

    float m0r = -1e30f, m1r = -1e30f, l0 = 0.f, l1 = 0.f;
    float oacc[4][4] = {};

    for (int kt = 0; kt < nt; kt++) {
        const int s = kt & 1;
        if (kt + 1 < nt) {
            unsigned sb = (s ^ 1) ? sb1 : sb0;
            size_t ka = kbase + (size_t)(kt + 1) * 64 * HD;
            size_t va = vbase + (size_t)(kt + 1) * 64;
            cpasync16(sb + (OFF_KH + ks0) * 2, Kh + ka + kg0);
            cpasync16(sb + (OFF_KH + ks1) * 2, Kh + ka + kg1);
            cpasync16(sb + (OFF_KL + ks0) * 2, Kl + ka + kg0);
            cpasync16(sb + (OFF_KL + ks1) * 2, Kl + ka + kg1);
            cpasync16(sb + (OFF_VH + vs0) * 2, Vh + va + vg0);
            cpasync16(sb + (OFF_VH + vs1) * 2, Vh + va + vg1);
            cpasync16(sb + (OFF_VL + vs0) * 2, Vl + va + vg0);
            cpasync16(sb + (OFF_VL + vs1) * 2, Vl + va + vg1);
            asm volatile("cp.async.commit_group;");
            asm volatile("cp.async.wait_group 1;" ::: "memory");
        } else {
            asm volatile("cp.async.wait_group 0;" ::: "memory");
        }
        __syncthreads();

        const bf16* Ks0 = &KV[s][OFF_KH];
        const bf16* Ks1 = &KV[s][OFF_KL];
        const bf16* Vs0 = &KV[s][OFF_VH];
        const bf16* Vs1 = &KV[s][OFF_VL];

        float sreg[8][4];
        #pragma unroll
        for (int nb = 0; nb < 8; nb++)
            sreg[nb][0] = sreg[nb][1] = sreg[nb][2] = sreg[nb][3] = 0.f;

        #pragma unroll
        for (int c = 0; c < 2; c++) {
            #pragma unroll
            for (int jp = 0; jp < 4; jp++) {
                unsigned kh4[4], kl4[4];
                ldsm4(kh4, &Ks0[(jp * 16 + brow) * QSTR + c * 16 + bcol]);
                ldsm4(kl4, &Ks1[(jp * 16 + brow) * QSTR + c * 16 + bcol]);
                mma16816(sreg[2*jp],   qf[0][c], kh4[0], kh4[1]);
                mma16816(sreg[2*jp],   qf[1][c], kh4[0], kh4[1]);
                mma16816(sreg[2*jp],   qf[0][c], kl4[0], kl4[1]);
                mma16816(sreg[2*jp+1], qf[0][c], kh4[2], kh4[3]);
                mma16816(sreg[2*jp+1], qf[1][c], kh4[2], kh4[3]);
                mma16816(sreg[2*jp+1], qf[0][c], kl4[2], kl4[3]);
            }
        }

        // online softmax in log2 domain (Q pre-scaled by GAMMA*log2e)
        float mx0 = sreg[0][0], mx1 = sreg[0][2];
        #pragma unroll
        for (int nb = 0; nb < 8; nb++) {
            mx0 = fmaxf(mx0, fmaxf(sreg[nb][0], sreg[nb][1]));
            mx1 = fmaxf(mx1, fmaxf(sreg[nb][2], sreg[nb][3]));
        }
        mx0 = fmaxf(mx0, __shfl_xor_sync(~0u, mx0, 1));
        mx0 = fmaxf(mx0, __shfl_xor_sync(~0u, mx0, 2));
        mx1 = fmaxf(mx1, __shfl_xor_sync(~0u, mx1, 1));
        mx1 = fmaxf(mx1, __shfl_xor_sync(~0u, mx1, 2));
        float nm0 = fmaxf(m0r, mx0), nm1 = fmaxf(m1r, mx1);
        float sc0 = exp2f(m0r - nm0), sc1 = exp2f(m1r - nm1);
        m0r = nm0; m1r = nm1;
        float rs0 = 0.f, rs1 = 0.f;
        #pragma unroll
        for (int nb = 0; nb < 8; nb++) {
            sreg[nb][0] = exp2f(sreg[nb][0] - nm0);
            sreg[nb][1] = exp2f(sreg[nb][1] - nm0);
            sreg[nb][2] = exp2f(sreg[nb][2] - nm1);
            sreg[nb][3] = exp2f(sreg[nb][3] - nm1);
            rs0 += sreg[nb][0] + sreg[nb][1];
            rs1 += sreg[nb][2] + sreg[nb][3];
        }
        rs0 += __shfl_xor_sync(~0u, rs0, 1);
        rs0 += __shfl_xor_sync(~0u, rs0, 2);
        rs1 += __shfl_xor_sync(~0u, rs1, 1);
        rs1 += __shfl_xor_sync(~0u, rs1, 2);
        l0 = l0 * sc0 + rs0;  l1 = l1 * sc1 + rs1;
        #pragma unroll
        for (int nb = 0; nb < 4; nb++) {
            oacc[nb][0] *= sc0; oacc[nb][1] *= sc0;
            oacc[nb][2] *= sc1; oacc[nb][3] *= sc1;
        }

        // O += P V  (packed P split), bf16x3
        #pragma unroll
        for (int c = 0; c < 4; c++) {
            unsigned pah[4], pal[4];
            #pragma unroll
            for (int r4 = 0; r4 < 4; r4++) {
                int nb = 2 * c + (r4 >> 1);
                int pr = (r4 & 1) * 2;
                psplit2(sreg[nb][pr], sreg[nb][pr + 1], pah[r4], pal[r4]);
            }
            #pragma unroll
            for (int np = 0; np < 2; np++) {
                unsigned vh4[4], vl4[4];
                ldsm4(vh4, &Vs0[(np * 16 + brow) * VSTR + c * 16 + bcol]);
                ldsm4(vl4, &Vs1[(np * 16 + brow) * VSTR + c * 16 + bcol]);
                mma16816(oacc[2*np],   pah, vh4[0], vh4[1]);
                mma16816(oacc[2*np],   pal, vh4[0], vh4[1]);
                mma16816(oacc[2*np],   pah, vl4[0], vl4[1]);
                mma16816(oacc[2*np+1], pah, vh4[2], vh4[3]);
                mma16816(oacc[2*np+1], pal, vh4[2], vh4[3]);
                mma16816(oacc[2*np+1], pah, vl4[2], vl4[3]);
            }
        }
        __syncthreads();
    }

    float inv0 = 1.f / l0, inv1 = 1.f / l1;
    int r = lane >> 2;
    int qg = q0 + w * 16 + r;
    size_t ob = (size_t)bh * NQ * HD;
    #pragma unroll
    for (int nb = 0; nb < 4; nb++) {
        int d = nb * 8 + (lane & 3) * 2;
        float2 v0 = make_float2(oacc[nb][0] * inv0, oacc[nb][1] * inv0);
        float2 v1 = make_float2(oacc[nb][2] * inv1, oacc[nb][3] * inv1);
        *(float2*)&O[ob + (size_t)qg * HD + d]       = v0;
        *(float2*)&O[ob + (size_t)(qg + 8) * HD + d] = v1;
    }
}

// ============================== launcher ==================================
extern "C" void kernel_launch(void* const* d_in, const int* in_sizes, int n_in,
                              void* d_out, int out_size)
{
    (void)out_size;
    const float *x=0, *y=0, *wxq=0, *bxq=0, *wyq=0, *byq=0,
                *wpx=0, *bpx=0, *wpy=0, *bpy=0;
    for (int i = 0; i < n_in; i++) {
        const float* p = (const float*)d_in[i];
        switch (in_sizes[i]) {
            case 2097152: x = p;   break;
            case 1048576: y = p;   break;
            case 98304:   wxq = p; break;
            case 196608:  wyq = p; break;
            case 32768:   wpx = p; break;
            case 65536:   wpy = p; break;
            case 256:     bpx = p; break;
            case 512:     bpy = p; break;
            case 384:     if (!bxq) bxq = p; else byq = p; break;
            default: break;
        }
    }
    float* out = (float*)d_out;

    split_w_kernel<<<288, 256>>>(wxq, wyq);
    presplit_x_kernel<<<3072, 256>>>(x, y);
    qkv_mma4_kernel<<<240, 256>>>(bxq, byq);
    attn_mma_kernel<<<640, 128>>>();
    gemm_proj_kernel<<<768, 256>>>(wpx, bpx, x, wpy, bpy, y, out);
}

// round 12
// speedup vs baseline: 1.2604x; 1.1239x over previous
#include <cuda_runtime.h>
#include <cuda_bf16.h>

#define X_CH   256
#define Y_CH   512
#define DIM    128
#define NHEAD  4
#define HD     32
#define HWX    4096
#define HWY    1024
#define BATCH  2
#define GAMMA  0.17677669529663687f
#define GAMMA_L2E (0.17677669529663687f * 1.4426950408889634f)

typedef __nv_bfloat16 bf16;

// ---------------- scratch (device globals; no allocation) ----------------
static __device__ __align__(16) bf16 g_qxh[BATCH*NHEAD*HWX*HD], g_qxl[BATCH*NHEAD*HWX*HD];
static __device__ __align__(16) bf16 g_kxh[BATCH*NHEAD*HWX*HD], g_kxl[BATCH*NHEAD*HWX*HD];
static __device__ __align__(16) bf16 g_vxh[BATCH*NHEAD*HWX*HD], g_vxl[BATCH*NHEAD*HWX*HD];
static __device__ __align__(16) bf16 g_qyh[BATCH*NHEAD*HWY*HD], g_qyl[BATCH*NHEAD*HWY*HD];
static __device__ __align__(16) bf16 g_kyh[BATCH*NHEAD*HWY*HD], g_kyl[BATCH*NHEAD*HWY*HD];
static __device__ __align__(16) bf16 g_vyh[BATCH*NHEAD*HWY*HD], g_vyl[BATCH*NHEAD*HWY*HD];
static __device__ float g_ax[BATCH*NHEAD*HWX*HD];   // attention out [b,h,p,d]
static __device__ float g_ay[BATCH*NHEAD*HWY*HD];
// pre-split QKV weights [M][K] and inputs [B][C][N], bf16 hi/lo
static __device__ __align__(16) bf16 g_wxqh[384*X_CH], g_wxql[384*X_CH];
static __device__ __align__(16) bf16 g_wyqh[384*Y_CH], g_wyql[384*Y_CH];
static __device__ __align__(16) bf16 g_xsh[BATCH*X_CH*HWX], g_xsl[BATCH*X_CH*HWX];
static __device__ __align__(16) bf16 g_ysh[BATCH*Y_CH*HWY], g_ysl[BATCH*Y_CH*HWY];
// split-K partials for dir1 (y attends x): 4 splits, [sp][bh][q]
static __device__ __align__(16) float  g_pacc[4*BATCH*NHEAD*HWY*HD];   // 4MB
static __device__ __align__(16) float2 g_pml[4*BATCH*NHEAD*HWY];       // (m,l)

__device__ __forceinline__ void bsplit(float v, bf16& h, bf16& l) {
    h = __float2bfloat16(v);
    l = __float2bfloat16(v - __bfloat162float(h));
}
__device__ __forceinline__ unsigned pack2(bf16 a, bf16 b) {
    return (unsigned)__bfloat16_as_ushort(a) | ((unsigned)__bfloat16_as_ushort(b) << 16);
}
__device__ __forceinline__ void psplit2(float x0, float x1, unsigned& ph, unsigned& pl) {
    unsigned h;
    asm("cvt.rn.bf16x2.f32 %0, %1, %2;" : "=r"(h) : "f"(x1), "f"(x0));
    float h0 = __uint_as_float(h << 16);
    float h1 = __uint_as_float(h & 0xffff0000u);
    float e0 = x0 - h0, e1 = x1 - h1;
    asm("cvt.rn.bf16x2.f32 %0, %1, %2;" : "=r"(pl) : "f"(e1), "f"(e0));
    ph = h;
}

// ---------------- prep: split QKV weights (validated) ----------------
__global__ void __launch_bounds__(256) split_w_kernel(
    const float* __restrict__ s0, const float* __restrict__ s1)
{
    int e = (blockIdx.x * 256 + threadIdx.x) * 4;
    const float* s; bf16 *dh, *dl;
    if (e < 98304) { s = s0; dh = g_wxqh; dl = g_wxql; }
    else           { e -= 98304; s = s1; dh = g_wyqh; dl = g_wyql; }
    float4 v = *(const float4*)(s + e);
    bf16 h0,l0,h1,l1,h2,l2,h3,l3;
    bsplit(v.x,h0,l0); bsplit(v.y,h1,l1); bsplit(v.z,h2,l2); bsplit(v.w,h3,l3);
    *(uint2*)(dh + e) = make_uint2(pack2(h0,h1), pack2(h2,h3));
    *(uint2*)(dl + e) = make_uint2(pack2(l0,l1), pack2(l2,l3));
}

// ---------------- prep: split inputs elementwise (validated) ----------
__global__ void __launch_bounds__(256) presplit_x_kernel(
    const float* __restrict__ x, const float* __restrict__ y)
{
    int e = (blockIdx.x * 256 + threadIdx.x) * 4;
    const float* s; bf16 *dh, *dl;
    if (e < BATCH*X_CH*HWX) { s = x; dh = g_xsh; dl = g_xsl; }
    else { e -= BATCH*X_CH*HWX; s = y; dh = g_ysh; dl = g_ysl; }
    float4 v = *(const float4*)(s + e);
    bf16 h0,l0,h1,l1,h2,l2,h3,l3;
    bsplit(v.x,h0,l0); bsplit(v.y,h1,l1); bsplit(v.z,h2,l2); bsplit(v.w,h3,l3);
    *(uint2*)(dh + e) = make_uint2(pack2(h0,h1), pack2(h2,h3));
    *(uint2*)(dl + e) = make_uint2(pack2(l0,l1), pack2(l2,l3));
}

// ---------------- MMA helpers ----------------
__device__ __forceinline__ void ldsm4(unsigned r[4], const void* p) {
    unsigned a = (unsigned)__cvta_generic_to_shared(p);
    asm volatile("ldmatrix.sync.aligned.m8n8.x4.shared.b16 {%0,%1,%2,%3}, [%4];"
        : "=r"(r[0]), "=r"(r[1]), "=r"(r[2]), "=r"(r[3]) : "r"(a));
}
__device__ __forceinline__ void ldsm4t(unsigned r[4], const void* p) {
    unsigned a = (unsigned)__cvta_generic_to_shared(p);
    asm volatile("ldmatrix.sync.aligned.m8n8.x4.trans.shared.b16 {%0,%1,%2,%3}, [%4];"
        : "=r"(r[0]), "=r"(r[1]), "=r"(r[2]), "=r"(r[3]) : "r"(a));
}
__device__ __forceinline__ void mma16816(float c[4], const unsigned a[4],
                                         unsigned b0, unsigned b1) {
    asm volatile("mma.sync.aligned.m16n8k16.row.col.f32.bf16.bf16.f32 "
        "{%0,%1,%2,%3}, {%4,%5,%6,%7}, {%8,%9}, {%0,%1,%2,%3};"
        : "+f"(c[0]), "+f"(c[1]), "+f"(c[2]), "+f"(c[3])
        : "r"(a[0]), "r"(a[1]), "r"(a[2]), "r"(a[3]), "r"(b0), "r"(b1));
}
__device__ __forceinline__ void cpasync16(unsigned dst, const void* src) {
    asm volatile("cp.async.ca.shared.global [%0], [%1], 16;" :: "r"(dst), "l"(src));
}

#define ASTR 24
#define BSTR 136
#define ST_A 3072
#define ST_B 2176
#define ST_TOTAL 10496

// ====== QKV tensor-core GEMM v4 (validated round-9/10) ====================
__global__ void __launch_bounds__(256) qkv_mma4_kernel(
    const float* __restrict__ bx, const float* __restrict__ by_)
{
    __shared__ __align__(16) char SMB[41984];
    bf16* SM = (bf16*)SMB;
    float* Cst = (float*)SMB;

    const bf16 *Wh, *Wl, *Xh, *Xl;
    const float* bias;
    bf16 *Qh_, *Ql_, *Kh_, *Kl_, *Vh_, *Vl_;
    int N, K, m0, n0, b;
    int blk = blockIdx.x;
    if (blk < 48) {
        N = HWY; K = Y_CH;
        b = blk / 24; int r = blk % 24; m0 = (r % 3) * 128; n0 = (r / 3) * 128;
        Wh = g_wyqh; Wl = g_wyql;
        Xh = g_ysh + (size_t)b * K * N; Xl = g_ysl + (size_t)b * K * N;
        bias = by_;
        Qh_=g_qyh; Ql_=g_qyl; Kh_=g_kyh; Kl_=g_kyl; Vh_=g_vyh; Vl_=g_vyl;
    } else {
        blk -= 48;
        N = HWX; K = X_CH;
        b = blk / 96; int r = blk % 96; m0 = (r % 3) * 128; n0 = (r / 3) * 128;
        Wh = g_wxqh; Wl = g_wxql;
        Xh = g_xsh + (size_t)b * K * N; Xl = g_xsl + (size_t)b * K * N;
        bias = bx;
        Qh_=g_qxh; Ql_=g_qxl; Kh_=g_kxh; Kl_=g_kxl; Vh_=g_vxh; Vl_=g_vxl;
    }

    const int tid = threadIdx.x, lane = tid & 31;
    const int w = tid >> 5;
    const int wm = w & 3, wn = w >> 2;
    const int arow = (lane & 7) + ((lane & 8) ? 8 : 0);
    const int acol = (lane & 16) ? 8 : 0;
    const int bkrow = (lane & 7) + ((lane & 8) ? 8 : 0);
    const int bncol = (lane & 16) ? 8 : 0;

    const unsigned sbase = (unsigned)__cvta_generic_to_shared(SMB);

    auto fill = [&](int s, int kc) {
        #pragma unroll
        for (int it = 0; it < 2; it++) {
            int id = tid + it * 256;
            int part = id & 1, rid = id >> 1;
            int row = rid >> 1, cc = rid & 1;
            unsigned adst = sbase + (unsigned)(s*ST_TOTAL + part*ST_A + row*ASTR + cc*8) * 2;
            cpasync16(adst, (part ? Wl : Wh) + (size_t)(m0 + row) * K + kc*16 + cc*8);
            int krow = rid >> 4, nc = rid & 15;
            unsigned bdst = sbase + (unsigned)(s*ST_TOTAL + 2*ST_A + part*ST_B + krow*BSTR + nc*8) * 2;
            cpasync16(bdst, (part ? Xl : Xh) + (size_t)(kc*16 + krow) * N + n0 + nc*8);
        }
        asm volatile("cp.async.commit_group;");
    };

    float acc[2][8][4] = {};
    const int nkc = K >> 4;

    fill(0, 0);
    for (int kc = 0; kc < nkc; kc++) {
        const int s = kc & 1;
        if (kc + 1 < nkc) {
            fill(s ^ 1, kc + 1);
            asm volatile("cp.async.wait_group 1;" ::: "memory");
        } else {
            asm volatile("cp.async.wait_group 0;" ::: "memory");
        }
        __syncthreads();

        const bf16* Ah = SM + s*ST_TOTAL;
        const bf16* Al = Ah + ST_A;
        const bf16* Bh = SM + s*ST_TOTAL + 2*ST_A;
        const bf16* Bl = Bh + ST_B;

        unsigned ah[2][4], al[2][4];
        #pragma unroll
        for (int im = 0; im < 2; im++) {
            ldsm4(ah[im], &Ah[(wm*32 + im*16 + arow) * ASTR + acol]);
            ldsm4(al[im], &Al[(wm*32 + im*16 + arow) * ASTR + acol]);
        }
        #pragma unroll
        for (int jn = 0; jn < 4; jn++) {
            unsigned bh4[4], bl4[4];
            const int boff = bkrow * BSTR + wn*64 + jn*16 + bncol;
            ldsm4t(bh4, &Bh[boff]);
            ldsm4t(bl4, &Bl[boff]);
            #pragma unroll
            for (int im = 0; im < 2; im++) {
                mma16816(acc[im][2*jn],   ah[im], bh4[0], bh4[1]);
                mma16816(acc[im][2*jn],   al[im], bh4[0], bh4[1]);
                mma16816(acc[im][2*jn],   ah[im], bl4[0], bl4[1]);
                mma16816(acc[im][2*jn+1], ah[im], bh4[2], bh4[3]);
                mma16816(acc[im][2*jn+1], al[im], bh4[2], bh4[3]);
                mma16816(acc[im][2*jn+1], ah[im], bl4[2], bl4[3]);
            }
        }
        __syncthreads();
    }

    const int r = lane >> 2, cq = (lane & 3) * 2;
    #pragma unroll
    for (int im = 0; im < 2; im++) {
        __syncthreads();
        #pragma unroll
        for (int j8 = 0; j8 < 8; j8++) {
            int col = wn*64 + j8*8 + cq;
            Cst[(wm*16 + r) * 128 + col]         = acc[im][j8][0];
            Cst[(wm*16 + r) * 128 + col + 1]     = acc[im][j8][1];
            Cst[(wm*16 + r + 8) * 128 + col]     = acc[im][j8][2];
            Cst[(wm*16 + r + 8) * 128 + col + 1] = acc[im][j8][3];
        }
        __syncthreads();
        for (int idx = tid; idx < 64*128; idx += 256) {
            int srow = idx >> 7, scol = idx & 127;
            int o = m0 + (srow >> 4) * 32 + im*16 + (srow & 15);
            int n = n0 + scol;
            float v = Cst[idx] + bias[o];
            int t = o >> 7, h = (o & 127) >> 5, d = o & 31;
            bf16 hh, ll;
            if (t == 0) {
                bsplit(v * GAMMA_L2E, hh, ll);
                size_t i2 = ((size_t)(b*NHEAD + h) * N + n) * HD + d;
                Qh_[i2] = hh;  Ql_[i2] = ll;
            } else if (t == 1) {
                bsplit(v, hh, ll);
                size_t i2 = ((size_t)(b*NHEAD + h) * N + n) * HD + d;
                Kh_[i2] = hh;  Kl_[i2] = ll;
            } else {
                bsplit(v, hh, ll);
                size_t i2 = ((size_t)(b*NHEAD + h) * HD + d) * N + n;
                Vh_[i2] = hh;  Vl_[i2] = ll;
            }
        }
    }
}

// ============ merged proj GEMM (fp32, validated round-6) ==================
__global__ void __launch_bounds__(256) gemm_proj_kernel(
    const float* __restrict__ Wx, const float* __restrict__ bpx, const float* __restrict__ Rx,
    const float* __restrict__ Wy, const float* __restrict__ bpy, const float* __restrict__ Ry,
    float* __restrict__ outp)
{
    const float *W, *bias, *Res, *Att;
    float* Out;
    int OC, N, b, m0, n0;
    int blk = blockIdx.x;
    if (blk < 256) {
        OC = Y_CH; N = HWY; W = Wy; bias = bpy; Res = Ry; Att = g_ay;
        Out = outp + (size_t)BATCH * X_CH * HWX;
        b = blk / 128; int r = blk % 128; m0 = (r % 8) * 64; n0 = (r / 8) * 64;
    } else {
        blk -= 256;
        OC = X_CH; N = HWX; W = Wx; bias = bpx; Res = Rx; Att = g_ax;
        Out = outp;
        b = blk / 256; int r = blk % 256; m0 = (r % 4) * 64; n0 = (r / 4) * 64;
    }

    __shared__ __align__(16) float As[16][64];
    __shared__ __align__(16) float Bs[16][64];

    const int tid = threadIdx.x;
    const int ty = tid >> 4, tx = tid & 15;
    const int am = tid >> 2, ak = (tid & 3) << 2;
    const int bn_ = tid >> 2, bkq = (tid & 3) << 2;

    float acc[4][4] = {};

    for (int k0 = 0; k0 < DIM; k0 += 16) {
        float4 av = *(const float4*)(W + (size_t)(m0 + am) * DIM + k0 + ak);
        int c = k0 + bkq;
        int h = c >> 5, d = c & 31;
        float4 bv = *(const float4*)(Att + ((size_t)(b * NHEAD + h) * N + n0 + bn_) * HD + d);
        As[ak+0][am] = av.x; As[ak+1][am] = av.y; As[ak+2][am] = av.z; As[ak+3][am] = av.w;
        Bs[bkq+0][bn_] = bv.x; Bs[bkq+1][bn_] = bv.y; Bs[bkq+2][bn_] = bv.z; Bs[bkq+3][bn_] = bv.w;
        __syncthreads();
        #pragma unroll
        for (int kk = 0; kk < 16; kk++) {
            float4 a4 = *(const float4*)(&As[kk][ty << 2]);
            float4 b4 = *(const float4*)(&Bs[kk][tx << 2]);
            float ar[4] = {a4.x, a4.y, a4.z, a4.w};
            float br[4] = {b4.x, b4.y, b4.z, b4.w};
            #pragma unroll
            for (int i = 0; i < 4; i++)
                #pragma unroll
                for (int j = 0; j < 4; j++)
                    acc[i][j] += ar[i] * br[j];
        }
        __syncthreads();
    }

    #pragma unroll
    for (int i = 0; i < 4; i++) {
        int o = m0 + (ty << 2) + i;
        float bval = bias[o];
        size_t off = ((size_t)b * OC + o) * N + n0 + (tx << 2);
        float4 rr = *(const float4*)(Res + off);
        float4 v;
        v.x = acc[i][0] + bval + rr.x;
        v.y = acc[i][1] + bval + rr.y;
        v.z = acc[i][2] + bval + rr.z;
        v.w = acc[i][3] + bval + rr.w;
        *(float4*)(Out + off) = v;
    }
}

// ====== MMA flash attention: split-K dir1 (4 splits), exp2 softmax =========
#define QSTR 40
#define VSTR 72
#define OFF_KH 0
#define OFF_KL 2560
#define OFF_VH 5120
#define OFF_VL 7424
#define STAGE_ELEMS 9728

// blocks [0,512): dir1 = 8 bh x 16 qtiles x 4 splits (16 tiles each).
// blocks [512,1024): dir0 = 8 bh x 64 qtiles (16 tiles each). Uniform work.
__global__ void __launch_bounds__(128) attn_mma_kernel()
{
    __shared__ __align__(16) bf16 KV[2][STAGE_ELEMS];

    int blk = blockIdx.x;
    const bf16 *Qh, *Ql, *Kh, *Kl, *Vh, *Vl; float* O = nullptr;
    int NQ, NK, bh, q0, kt0, sp = 0;
    bool split;
    if (blk < 512) {   // dir1: y attends x, 4-way split-K
        split = true;
        bh = blk >> 6;                 // 0..7
        int r2 = blk & 63;
        q0 = (r2 >> 2) * 64;           // 16 q-tiles
        sp = r2 & 3;                   // 4 splits
        kt0 = sp * 16;                 // 16 tiles per split
        NQ = HWY; NK = HWX;
        Qh=g_qyh; Ql=g_qyl; Kh=g_kxh; Kl=g_kxl; Vh=g_vxh; Vl=g_vxl;
    } else {           // dir0: x attends y
        split = false;
        blk -= 512;
        bh = blk >> 6; q0 = (blk & 63) * 64; kt0 = 0; NQ = HWX; NK = HWY;
        Qh=g_qxh; Ql=g_qxl; Kh=g_kyh; Kl=g_kyl; Vh=g_vyh; Vl=g_vyl; O=g_ax;
    }
    const int nt = 16;

    const int tid = threadIdx.x, w = tid >> 5, lane = tid & 31;
    const size_t kbase = (size_t)bh * NK * HD;
    const size_t vbase = (size_t)bh * HD * NK;

    const int e0 = tid * 8, e1 = (tid + 128) * 8;
    const int ks0 = (e0 >> 5) * QSTR + (e0 & 31);
    const int ks1 = (e1 >> 5) * QSTR + (e1 & 31);
    const int vs0 = (e0 >> 6) * VSTR + (e0 & 63);
    const int vs1 = (e1 >> 6) * VSTR + (e1 & 63);
    const size_t kg0 = (size_t)(e0 >> 5) * HD + (e0 & 31);
    const size_t kg1 = (size_t)(e1 >> 5) * HD + (e1 & 31);
    const size_t vg0 = (size_t)(e0 >> 6) * NK + (e0 & 63);
    const size_t vg1 = (size_t)(e1 >> 6) * NK + (e1 & 63);

    unsigned sb0 = (unsigned)__cvta_generic_to_shared(&KV[0][0]);
    unsigned sb1 = (unsigned)__cvta_generic_to_shared(&KV[1][0]);

    {
        size_t ka = kbase + (size_t)kt0 * 64 * HD;
        size_t va = vbase + (size_t)kt0 * 64;
        cpasync16(sb0 + (OFF_KH + ks0) * 2, Kh + ka + kg0);
        cpasync16(sb0 + (OFF_KH + ks1) * 2, Kh + ka + kg1);
        cpasync16(sb0 + (OFF_KL + ks0) * 2, Kl + ka + kg0);
        cpasync16(sb0 + (OFF_KL + ks1) * 2, Kl + ka + kg1);
        cpasync16(sb0 + (OFF_VH + vs0) * 2, Vh + va + vg0);
        cpasync16(sb0 + (OFF_VH + vs1) * 2, Vh + va + vg1);
        cpasync16(sb0 + (OFF_VL + vs0) * 2, Vl + va + vg0);
        cpasync16(sb0 + (OFF_VL + vs1) * 2, Vl + va + vg1);
        asm volatile("cp.async.commit_group;");
    }

    {
        bf16* Qsh = &KV[1][0];
        bf16* Qsl = &KV[1][2560];
        const size_t qb = (size_t)bh * NQ * HD + (size_t)q0 * HD;
        #pragma unroll
        for (int it = 0; it < 2; it++) {
            int e = (tid + it * 128) * 8;
            int row = e >> 5, col = e & 31;
            *(uint4*)&Qsh[row * QSTR + col] = *(const uint4*)(Qh + qb + (size_t)row * HD + col);
            *(uint4*)&Qsl[row * QSTR + col] = *(const uint4*)(Ql + qb + (size_t)row * HD + col);
        }
    }
    __syncthreads();

    const int arow = (lane & 7) + ((lane & 8) ? 8 : 0);
    const int acol = (lane & 16) ? 8 : 0;
    const int brow = (lane & 7) + ((lane & 16) ? 8 : 0);
    const int bcol = (lane & 8) ? 8 : 0;
    unsigned qf[2][2][4];
    #pragma unroll
    for (int p = 0; p < 2; p++)
        #pragma unroll
        for (int c = 0; c < 2; c++)
            ldsm4(qf[p][c], &KV[1][p * 2560 + (w * 16 + arow) * QSTR + c * 16 + acol]);
    __syncthreads();

    float m0r = -1e30f, m1r = -1e30f, l0 = 0.f, l1 = 0.f;
    float oacc[4][4] = {};

    for (int i = 0; i < nt; i++) {
        const int s = i & 1;
        if (i + 1 < nt) {
            unsigned sb = (s ^ 1) ? sb1 : sb0;
            size_t ka = kbase + (size_t)(kt0 + i + 1) * 64 * HD;
            size_t va = vbase + (size_t)(kt0 + i + 1) * 64;
            cpasync16(sb + (OFF_KH + ks0) * 2, Kh + ka + kg0);
            cpasync16(sb + (OFF_KH + ks1) * 2, Kh + ka + kg1);
            cpasync16(sb + (OFF_KL + ks0) * 2, Kl + ka + kg0);
            cpasync16(sb + (OFF_KL + ks1) * 2, Kl + ka + kg1);
            cpasync16(sb + (OFF_VH + vs0) * 2, Vh + va + vg0);
            cpasync16(sb + (OFF_VH + vs1) * 2, Vh + va + vg1);
            cpasync16(sb + (OFF_VL + vs0) * 2, Vl + va + vg0);
            cpasync16(sb + (OFF_VL + vs1) * 2, Vl + va + vg1);
            asm volatile("cp.async.commit_group;");
            asm volatile("cp.async.wait_group 1;" ::: "memory");
        } else {
            asm volatile("cp.async.wait_group 0;" ::: "memory");
        }
        __syncthreads();

        const bf16* Ks0 = &KV[s][OFF_KH];
        const bf16* Ks1 = &KV[s][OFF_KL];
        const bf16* Vs0 = &KV[s][OFF_VH];
        const bf16* Vs1 = &KV[s][OFF_VL];

        float sreg[8][4];
        #pragma unroll
        for (int nb = 0; nb < 8; nb++)
            sreg[nb][0] = sreg[nb][1] = sreg[nb][2] = sreg[nb][3] = 0.f;

        #pragma unroll
        for (int c = 0; c < 2; c++) {
            #pragma unroll
            for (int jp = 0; jp < 4; jp++) {
                unsigned kh4[4], kl4[4];
                ldsm4(kh4, &Ks0[(jp * 16 + brow) * QSTR + c * 16 + bcol]);
                ldsm4(kl4, &Ks1[(jp * 16 + brow) * QSTR + c * 16 + bcol]);
                mma16816(sreg[2*jp],   qf[0][c], kh4[0], kh4[1]);
                mma16816(sreg[2*jp],   qf[1][c], kh4[0], kh4[1]);
                mma16816(sreg[2*jp],   qf[0][c], kl4[0], kl4[1]);
                mma16816(sreg[2*jp+1], qf[0][c], kh4[2], kh4[3]);
                mma16816(sreg[2*jp+1], qf[1][c], kh4[2], kh4[3]);
                mma16816(sreg[2*jp+1], qf[0][c], kl4[2], kl4[3]);
            }
        }

        float mx0 = sreg[0][0], mx1 = sreg[0][2];
        #pragma unroll
        for (int nb = 0; nb < 8; nb++) {
            mx0 = fmaxf(mx0, fmaxf(sreg[nb][0], sreg[nb][1]));
            mx1 = fmaxf(mx1, fmaxf(sreg[nb][2], sreg[nb][3]));
        }
        mx0 = fmaxf(mx0, __shfl_xor_sync(~0u, mx0, 1));
        mx0 = fmaxf(mx0, __shfl_xor_sync(~0u, mx0, 2));
        mx1 = fmaxf(mx1, __shfl_xor_sync(~0u, mx1, 1));
        mx1 = fmaxf(mx1, __shfl_xor_sync(~0u, mx1, 2));
        float nm0 = fmaxf(m0r, mx0), nm1 = fmaxf(m1r, mx1);
        float sc0 = exp2f(m0r - nm0), sc1 = exp2f(m1r - nm1);
        m0r = nm0; m1r = nm1;
        float rs0 = 0.f, rs1 = 0.f;
        #pragma unroll
        for (int nb = 0; nb < 8; nb++) {
            sreg[nb][0] = exp2f(sreg[nb][0] - nm0);
            sreg[nb][1] = exp2f(sreg[nb][1] - nm0);
            sreg[nb][2] = exp2f(sreg[nb][2] - nm1);
            sreg[nb][3] = exp2f(sreg[nb][3] - nm1);
            rs0 += sreg[nb][0] + sreg[nb][1];
            rs1 += sreg[nb][2] + sreg[nb][3];
        }
        rs0 += __shfl_xor_sync(~0u, rs0, 1);
        rs0 += __shfl_xor_sync(~0u, rs0, 2);
        rs1 += __shfl_xor_sync(~0u, rs1, 1);
        rs1 += __shfl_xor_sync(~0u, rs1, 2);
        l0 = l0 * sc0 + rs0;  l1 = l1 * sc1 + rs1;
        #pragma unroll
        for (int nb = 0; nb < 4; nb++) {
            oacc[nb][0] *= sc0; oacc[nb][1] *= sc0;
            oacc[nb][2] *= sc1; oacc[nb][3] *= sc1;
        }

        #pragma unroll
        for (int c = 0; c < 4; c++) {
            unsigned pah[4], pal[4];
            #pragma unroll
            for (int r4 = 0; r4 < 4; r4++) {
                int nb = 2 * c + (r4 >> 1);
                int pr = (r4 & 1) * 2;
                psplit2(sreg[nb][pr], sreg[nb][pr + 1], pah[r4], pal[r4]);
            }
            #pragma unroll
            for (int np = 0; np < 2; np++) {
                unsigned vh4[4], vl4[4];
                ldsm4(vh4, &Vs0[(np * 16 + brow) * VSTR + c * 16 + bcol]);
                ldsm4(vl4, &Vs1[(np * 16 + brow) * VSTR + c * 16 + bcol]);
                mma16816(oacc[2*np],   pah, vh4[0], vh4[1]);
                mma16816(oacc[2*np],   pal, vh4[0], vh4[1]);
                mma16816(oacc[2*np],   pah, vl4[0], vl4[1]);
                mma16816(oacc[2*np+1], pah, vh4[2], vh4[3]);
                mma16816(oacc[2*np+1], pal, vh4[2], vh4[3]);
                mma16816(oacc[2*np+1], pah, vl4[2], vl4[3]);
            }
        }
        __syncthreads();
    }

    int r = lane >> 2;
    int qg = q0 + w * 16 + r;
    if (split) {
        size_t pb = ((size_t)sp * 8 + bh) * HWY;      // [sp][bh][q], sp<4, bh<8
        #pragma unroll
        for (int nb = 0; nb < 4; nb++) {
            int d = nb * 8 + (lane & 3) * 2;
            *(float2*)&g_pacc[(pb + qg) * HD + d]     = make_float2(oacc[nb][0], oacc[nb][1]);
            *(float2*)&g_pacc[(pb + qg + 8) * HD + d] = make_float2(oacc[nb][2], oacc[nb][3]);
        }
        if ((lane & 3) == 0) {
            g_pml[pb + qg]     = make_float2(m0r, l0);
            g_pml[pb + qg + 8] = make_float2(m1r, l1);
        }
    } else {
        float inv0 = 1.f / l0, inv1 = 1.f / l1;
        size_t ob = (size_t)bh * NQ * HD;
        #pragma unroll
        for (int nb = 0; nb < 4; nb++) {
            int d = nb * 8 + (lane & 3) * 2;
            float2 v0 = make_float2(oacc[nb][0] * inv0, oacc[nb][1] * inv0);
            float2 v1 = make_float2(oacc[nb][2] * inv1, oacc[nb][3] * inv1);
            *(float2*)&O[ob + (size_t)qg * HD + d]       = v0;
            *(float2*)&O[ob + (size_t)(qg + 8) * HD + d] = v1;
        }
    }
}

// ====== combine split-K partials for dir1 (4 splits, 8 bh) =================
__global__ void __launch_bounds__(128) attn_combine_kernel()
{
    int t = blockIdx.x * 128 + threadIdx.x;   // 8192 threads: (bh<8, q<1024)
    int bh = t >> 10, q = t & 1023;
    float2 ml[4];
    float M = -1e30f;
    #pragma unroll
    for (int s = 0; s < 4; s++) {
        ml[s] = g_pml[((size_t)s * 8 + bh) * HWY + q];
        M = fmaxf(M, ml[s].x);
    }
    float wgt[4], L = 0.f;
    #pragma unroll
    for (int s = 0; s < 4; s++) {
        wgt[s] = exp2f(ml[s].x - M);
        L += wgt[s] * ml[s].y;
    }
    float invL = 1.f / L;
    float* dst = g_ay + ((size_t)bh * HWY + q) * HD;
    #pragma unroll
    for (int d = 0; d < HD; d += 4) {
        float4 o = make_float4(0.f, 0.f, 0.f, 0.f);
        #pragma unroll
        for (int s = 0; s < 4; s++) {
            const float* a = g_pacc + (((size_t)s * 8 + bh) * HWY + q) * HD;
            float4 v = *(const float4*)(a + d);
            o.x += wgt[s] * v.x;  o.y += wgt[s] * v.y;
            o.z += wgt[s] * v.z;  o.w += wgt[s] * v.w;
        }
        o.x *= invL; o.y *= invL; o.z *= invL; o.w *= invL;
        *(float4*)(dst + d) = o;
    }
}

// ============================== launcher ==================================
extern "C" void kernel_launch(void* const* d_in, const int* in_sizes, int n_in,
                              void* d_out, int out_size)
{
    (void)out_size;
    const float *x=0, *y=0, *wxq=0, *bxq=0, *wyq=0, *byq=0,
                *wpx=0, *bpx=0, *wpy=0, *bpy=0;
    for (int i = 0; i < n_in; i++) {
        const float* p = (const float*)d_in[i];
        switch (in_sizes[i]) {
            case 2097152: x = p;   break;
            case 1048576: y = p;   break;
            case 98304:   wxq = p; break;
            case 196608:  wyq = p; break;
            case 32768:   wpx = p; break;
            case 65536:   wpy = p; break;
            case 256:     bpx = p; break;
            case 512:     bpy = p; break;
            case 384:     if (!bxq) bxq = p; else byq = p; break;
            default: break;
        }
    }
    float* out = (float*)d_out;

    split_w_kernel<<<288, 256>>>(wxq, wyq);
    presplit_x_kernel<<<3072, 256>>>(x, y);
    qkv_mma4_kernel<<<240, 256>>>(bxq, byq);
    attn_mma_kernel<<<1024, 128>>>();
    attn_combine_kernel<<<64, 128>>>();
    gemm_proj_kernel<<<768, 256>>>(wpx, bpx, x, wpy, bpy, y, out);
}

// round 13
// speedup vs baseline: 1.2963x; 1.0285x over previous
#include <cuda_runtime.h>
#include <cuda_bf16.h>

#define X_CH   256
#define Y_CH   512
#define DIM    128
#define NHEAD  4
#define HD     32
#define HWX    4096
#define HWY    1024
#define BATCH  2
#define GAMMA  0.17677669529663687f
#define GAMMA_L2E (0.17677669529663687f * 1.4426950408889634f)

typedef __nv_bfloat16 bf16;

// ---------------- scratch (device globals; no allocation) ----------------
static __device__ __align__(16) bf16 g_qxh[BATCH*NHEAD*HWX*HD], g_qxl[BATCH*NHEAD*HWX*HD];
static __device__ __align__(16) bf16 g_kxh[BATCH*NHEAD*HWX*HD], g_kxl[BATCH*NHEAD*HWX*HD];
static __device__ __align__(16) bf16 g_vxh[BATCH*NHEAD*HWX*HD], g_vxl[BATCH*NHEAD*HWX*HD];
static __device__ __align__(16) bf16 g_qyh[BATCH*NHEAD*HWY*HD], g_qyl[BATCH*NHEAD*HWY*HD];
static __device__ __align__(16) bf16 g_kyh[BATCH*NHEAD*HWY*HD], g_kyl[BATCH*NHEAD*HWY*HD];
static __device__ __align__(16) bf16 g_vyh[BATCH*NHEAD*HWY*HD], g_vyl[BATCH*NHEAD*HWY*HD];
static __device__ float g_ax[BATCH*NHEAD*HWX*HD];
static __device__ float g_ay[BATCH*NHEAD*HWY*HD];
static __device__ __align__(16) bf16 g_wxqh[384*X_CH], g_wxql[384*X_CH];
static __device__ __align__(16) bf16 g_wyqh[384*Y_CH], g_wyql[384*Y_CH];
static __device__ __align__(16) bf16 g_xsh[BATCH*X_CH*HWX], g_xsl[BATCH*X_CH*HWX];
static __device__ __align__(16) bf16 g_ysh[BATCH*Y_CH*HWY], g_ysl[BATCH*Y_CH*HWY];
static __device__ __align__(16) float  g_pacc[4*BATCH*NHEAD*HWY*HD];
static __device__ __align__(16) float2 g_pml[4*BATCH*NHEAD*HWY];

__device__ __forceinline__ void bsplit(float v, bf16& h, bf16& l) {
    h = __float2bfloat16(v);
    l = __float2bfloat16(v - __bfloat162float(h));
}
__device__ __forceinline__ unsigned pack2(bf16 a, bf16 b) {
    return (unsigned)__bfloat16_as_ushort(a) | ((unsigned)__bfloat16_as_ushort(b) << 16);
}
__device__ __forceinline__ void psplit2(float x0, float x1, unsigned& ph, unsigned& pl) {
    unsigned h;
    asm("cvt.rn.bf16x2.f32 %0, %1, %2;" : "=r"(h) : "f"(x1), "f"(x0));
    float h0 = __uint_as_float(h << 16);
    float h1 = __uint_as_float(h & 0xffff0000u);
    float e0 = x0 - h0, e1 = x1 - h1;
    asm("cvt.rn.bf16x2.f32 %0, %1, %2;" : "=r"(pl) : "f"(e1), "f"(e0));
    ph = h;
}

// ---------------- prep: split QKV weights (validated) ----------------
__global__ void __launch_bounds__(256) split_w_kernel(
    const float* __restrict__ s0, const float* __restrict__ s1)
{
    int e = (blockIdx.x * 256 + threadIdx.x) * 4;
    const float* s; bf16 *dh, *dl;
    if (e < 98304) { s = s0; dh = g_wxqh; dl = g_wxql; }
    else           { e -= 98304; s = s1; dh = g_wyqh; dl = g_wyql; }
    float4 v = *(const float4*)(s + e);
    bf16 h0,l0,h1,l1,h2,l2,h3,l3;
    bsplit(v.x,h0,l0); bsplit(v.y,h1,l1); bsplit(v.z,h2,l2); bsplit(v.w,h3,l3);
    *(uint2*)(dh + e) = make_uint2(pack2(h0,h1), pack2(h2,h3));
    *(uint2*)(dl + e) = make_uint2(pack2(l0,l1), pack2(l2,l3));
}

// ---------------- prep: split inputs elementwise (validated) ----------
__global__ void __launch_bounds__(256) presplit_x_kernel(
    const float* __restrict__ x, const float* __restrict__ y)
{
    int e = (blockIdx.x * 256 + threadIdx.x) * 4;
    const float* s; bf16 *dh, *dl;
    if (e < BATCH*X_CH*HWX) { s = x; dh = g_xsh; dl = g_xsl; }
    else { e -= BATCH*X_CH*HWX; s = y; dh = g_ysh; dl = g_ysl; }
    float4 v = *(const float4*)(s + e);
    bf16 h0,l0,h1,l1,h2,l2,h3,l3;
    bsplit(v.x,h0,l0); bsplit(v.y,h1,l1); bsplit(v.z,h2,l2); bsplit(v.w,h3,l3);
    *(uint2*)(dh + e) = make_uint2(pack2(h0,h1), pack2(h2,h3));
    *(uint2*)(dl + e) = make_uint2(pack2(l0,l1), pack2(l2,l3));
}

// ---------------- MMA helpers ----------------
__device__ __forceinline__ void ldsm4(unsigned r[4], const void* p) {
    unsigned a = (unsigned)__cvta_generic_to_shared(p);
    asm volatile("ldmatrix.sync.aligned.m8n8.x4.shared.b16 {%0,%1,%2,%3}, [%4];"
        : "=r"(r[0]), "=r"(r[1]), "=r"(r[2]), "=r"(r[3]) : "r"(a));
}
__device__ __forceinline__ void ldsm4t(unsigned r[4], const void* p) {
    unsigned a = (unsigned)__cvta_generic_to_shared(p);
    asm volatile("ldmatrix.sync.aligned.m8n8.x4.trans.shared.b16 {%0,%1,%2,%3}, [%4];"
        : "=r"(r[0]), "=r"(r[1]), "=r"(r[2]), "=r"(r[3]) : "r"(a));
}
__device__ __forceinline__ void mma16816(float c[4], const unsigned a[4],
                                         unsigned b0, unsigned b1) {
    asm volatile("mma.sync.aligned.m16n8k16.row.col.f32.bf16.bf16.f32 "
        "{%0,%1,%2,%3}, {%4,%5,%6,%7}, {%8,%9}, {%0,%1,%2,%3};"
        : "+f"(c[0]), "+f"(c[1]), "+f"(c[2]), "+f"(c[3])
        : "r"(a[0]), "r"(a[1]), "r"(a[2]), "r"(a[3]), "r"(b0), "r"(b1));
}
__device__ __forceinline__ void cpasync16(unsigned dst, const void* src) {
    asm volatile("cp.async.ca.shared.global [%0], [%1], 16;" :: "r"(dst), "l"(src));
}

// ====== QKV tensor-core GEMM v5: 128m x 64n tiles, 480 blocks =============
#define ASTR 24
#define BSTR5 72     // B tile [16k][64n] row stride
#define ST_A 3072    // A part elems (128*24)
#define ST_B5 1152   // B part elems (16*72)
#define ST_TOT5 8448 // 2*ST_A + 2*ST_B5

// blocks [0,96): y (K=512, first: 2b x 3m x 16n); [96,480): x (2b x 3m x 64n)
__global__ void __launch_bounds__(256) qkv_mma5_kernel(
    const float* __restrict__ bx, const float* __restrict__ by_)
{
    __shared__ __align__(16) char SMB[33792];   // 2 stages * 16896 B
    bf16* SM = (bf16*)SMB;
    float* Cst = (float*)SMB;                   // 64x64 fp32 = 16KB, reused

    const bf16 *Wh, *Wl, *Xh, *Xl;
    const float* bias;
    bf16 *Qh_, *Ql_, *Kh_, *Kl_, *Vh_, *Vl_;
    int N, K, m0, n0, b;
    int blk = blockIdx.x;
    if (blk < 96) {
        N = HWY; K = Y_CH;
        b = blk / 48; int r = blk % 48; m0 = (r % 3) * 128; n0 = (r / 3) * 64;
        Wh = g_wyqh; Wl = g_wyql;
        Xh = g_ysh + (size_t)b * K * N; Xl = g_ysl + (size_t)b * K * N;
        bias = by_;
        Qh_=g_qyh; Ql_=g_qyl; Kh_=g_kyh; Kl_=g_kyl; Vh_=g_vyh; Vl_=g_vyl;
    } else {
        blk -= 96;
        N = HWX; K = X_CH;
        b = blk / 192; int r = blk % 192; m0 = (r % 3) * 128; n0 = (r / 3) * 64;
        Wh = g_wxqh; Wl = g_wxql;
        Xh = g_xsh + (size_t)b * K * N; Xl = g_xsl + (size_t)b * K * N;
        bias = bx;
        Qh_=g_qxh; Ql_=g_qxl; Kh_=g_kxh; Kl_=g_kxl; Vh_=g_vxh; Vl_=g_vxl;
    }

    const int tid = threadIdx.x, lane = tid & 31;
    const int w = tid >> 5;
    const int wm = w & 3, wn = w >> 2;            // 4 m-warps x 2 n-warps(32 cols)
    const int arow = (lane & 7) + ((lane & 8) ? 8 : 0);
    const int acol = (lane & 16) ? 8 : 0;
    const int bkrow = (lane & 7) + ((lane & 8) ? 8 : 0);
    const int bncol = (lane & 16) ? 8 : 0;

    const unsigned sbase = (unsigned)__cvta_generic_to_shared(SMB);

    // stage-fill: 768 16B-chunks per stage, 3 per thread
    auto fill = [&](int s, int kc) {
        #pragma unroll
        for (int it = 0; it < 3; it++) {
            int id = tid + it * 256;               // 0..767
            if (id < 512) {                        // A: 2 parts x 128r x 2c
                int part = id & 1, rid = id >> 1;
                int row = rid >> 1, cc = rid & 1;
                unsigned adst = sbase + (unsigned)(s*ST_TOT5 + part*ST_A + row*ASTR + cc*8) * 2;
                cpasync16(adst, (part ? Wl : Wh) + (size_t)(m0 + row) * K + kc*16 + cc*8);
            } else {                               // B: 2 parts x 16k x 8c
                int j = id - 512;
                int part = j & 1, rid2 = j >> 1;   // 0..127
                int krow = rid2 >> 3, nc = rid2 & 7;
                unsigned bdst = sbase + (unsigned)(s*ST_TOT5 + 2*ST_A + part*ST_B5 + krow*BSTR5 + nc*8) * 2;
                cpasync16(bdst, (part ? Xl : Xh) + (size_t)(kc*16 + krow) * N + n0 + nc*8);
            }
        }
        asm volatile("cp.async.commit_group;");
    };

    float acc[2][4][4] = {};
    const int nkc = K >> 4;

    fill(0, 0);
    for (int kc = 0; kc < nkc; kc++) {
        const int s = kc & 1;
        if (kc + 1 < nkc) {
            fill(s ^ 1, kc + 1);
            asm volatile("cp.async.wait_group 1;" ::: "memory");
        } else {
            asm volatile("cp.async.wait_group 0;" ::: "memory");
        }
        __syncthreads();

        const bf16* Ah = SM + s*ST_TOT5;
        const bf16* Al = Ah + ST_A;
        const bf16* Bh = SM + s*ST_TOT5 + 2*ST_A;
        const bf16* Bl = Bh + ST_B5;

        unsigned ah[2][4], al[2][4];
        #pragma unroll
        for (int im = 0; im < 2; im++) {
            ldsm4(ah[im], &Ah[(wm*32 + im*16 + arow) * ASTR + acol]);
            ldsm4(al[im], &Al[(wm*32 + im*16 + arow) * ASTR + acol]);
        }
        #pragma unroll
        for (int jn = 0; jn < 2; jn++) {
            unsigned bh4[4], bl4[4];
            const int boff = bkrow * BSTR5 + wn*32 + jn*16 + bncol;
            ldsm4t(bh4, &Bh[boff]);
            ldsm4t(bl4, &Bl[boff]);
            #pragma unroll
            for (int im = 0; im < 2; im++) {
                mma16816(acc[im][2*jn],   ah[im], bh4[0], bh4[1]);
                mma16816(acc[im][2*jn],   al[im], bh4[0], bh4[1]);
                mma16816(acc[im][2*jn],   ah[im], bl4[0], bl4[1]);
                mma16816(acc[im][2*jn+1], ah[im], bh4[2], bh4[3]);
                mma16816(acc[im][2*jn+1], al[im], bh4[2], bh4[3]);
                mma16816(acc[im][2*jn+1], ah[im], bl4[2], bl4[3]);
            }
        }
        __syncthreads();
    }

    // staged epilogue: fragments -> smem fp32 (64x64) -> linear scatter
    const int r = lane >> 2, cq = (lane & 3) * 2;
    #pragma unroll
    for (int im = 0; im < 2; im++) {
        __syncthreads();
        #pragma unroll
        for (int j8 = 0; j8 < 4; j8++) {
            int col = wn*32 + j8*8 + cq;
            Cst[(wm*16 + r) * 64 + col]         = acc[im][j8][0];
            Cst[(wm*16 + r) * 64 + col + 1]     = acc[im][j8][1];
            Cst[(wm*16 + r + 8) * 64 + col]     = acc[im][j8][2];
            Cst[(wm*16 + r + 8) * 64 + col + 1] = acc[im][j8][3];
        }
        __syncthreads();
        for (int idx = tid; idx < 64*64; idx += 256) {
            int srow = idx >> 6, scol = idx & 63;
            int o = m0 + (srow >> 4) * 32 + im*16 + (srow & 15);
            int n = n0 + scol;
            float v = Cst[idx] + bias[o];
            int t = o >> 7, h = (o & 127) >> 5, d = o & 31;
            bf16 hh, ll;
            if (t == 0) {
                bsplit(v * GAMMA_L2E, hh, ll);
                size_t i2 = ((size_t)(b*NHEAD + h) * N + n) * HD + d;
                Qh_[i2] = hh;  Ql_[i2] = ll;
            } else if (t == 1) {
                bsplit(v, hh, ll);
                size_t i2 = ((size_t)(b*NHEAD + h) * N + n) * HD + d;
                Kh_[i2] = hh;  Kl_[i2] = ll;
            } else {
                bsplit(v, hh, ll);
                size_t i2 = ((size_t)(b*NHEAD + h) * HD + d) * N + n;
                Vh_[i2] = hh;  Vl_[i2] = ll;
            }
        }
    }
}

// ============ merged proj GEMM (fp32, validated round-6) ==================
__global__ void __launch_bounds__(256) gemm_proj_kernel(
    const float* __restrict__ Wx, const float* __restrict__ bpx, const float* __restrict__ Rx,
    const float* __restrict__ Wy, const float* __restrict__ bpy, const float* __restrict__ Ry,
    float* __restrict__ outp)
{
    const float *W, *bias, *Res, *Att;
    float* Out;
    int OC, N, b, m0, n0;
    int blk = blockIdx.x;
    if (blk < 256) {
        OC = Y_CH; N = HWY; W = Wy; bias = bpy; Res = Ry; Att = g_ay;
        Out = outp + (size_t)BATCH * X_CH * HWX;
        b = blk / 128; int r = blk % 128; m0 = (r % 8) * 64; n0 = (r / 8) * 64;
    } else {
        blk -= 256;
        OC = X_CH; N = HWX; W = Wx; bias = bpx; Res = Rx; Att = g_ax;
        Out = outp;
        b = blk / 256; int r = blk % 256; m0 = (r % 4) * 64; n0 = (r / 4) * 64;
    }

    __shared__ __align__(16) float As[16][64];
    __shared__ __align__(16) float Bs[16][64];

    const int tid = threadIdx.x;
    const int ty = tid >> 4, tx = tid & 15;
    const int am = tid >> 2, ak = (tid & 3) << 2;
    const int bn_ = tid >> 2, bkq = (tid & 3) << 2;

    float acc[4][4] = {};

    for (int k0 = 0; k0 < DIM; k0 += 16) {
        float4 av = *(const float4*)(W + (size_t)(m0 + am) * DIM + k0 + ak);
        int c = k0 + bkq;
        int h = c >> 5, d = c & 31;
        float4 bv = *(const float4*)(Att + ((size_t)(b * NHEAD + h) * N + n0 + bn_) * HD + d);
        As[ak+0][am] = av.x; As[ak+1][am] = av.y; As[ak+2][am] = av.z; As[ak+3][am] = av.w;
        Bs[bkq+0][bn_] = bv.x; Bs[bkq+1][bn_] = bv.y; Bs[bkq+2][bn_] = bv.z; Bs[bkq+3][bn_] = bv.w;
        __syncthreads();
        #pragma unroll
        for (int kk = 0; kk < 16; kk++) {
            float4 a4 = *(const float4*)(&As[kk][ty << 2]);
            float4 b4 = *(const float4*)(&Bs[kk][tx << 2]);
            float ar[4] = {a4.x, a4.y, a4.z, a4.w};
            float br[4] = {b4.x, b4.y, b4.z, b4.w};
            #pragma unroll
            for (int i = 0; i < 4; i++)
                #pragma unroll
                for (int j = 0; j < 4; j++)
                    acc[i][j] += ar[i] * br[j];
        }
        __syncthreads();
    }

    #pragma unroll
    for (int i = 0; i < 4; i++) {
        int o = m0 + (ty << 2) + i;
        float bval = bias[o];
        size_t off = ((size_t)b * OC + o) * N + n0 + (tx << 2);
        float4 rr = *(const float4*)(Res + off);
        float4 v;
        v.x = acc[i][0] + bval + rr.x;
        v.y = acc[i][1] + bval + rr.y;
        v.z = acc[i][2] + bval + rr.z;
        v.w = acc[i][3] + bval + rr.w;
        *(float4*)(Out + off) = v;
    }
}

// ====== MMA flash attention: split-K dir1 (validated round-12) =============
#define QSTR 40
#define VSTR 72
#define OFF_KH 0
#define OFF_KL 2560
#define OFF_VH 5120
#define OFF_VL 7424
#define STAGE_ELEMS 9728

__global__ void __launch_bounds__(128) attn_mma_kernel()
{
    __shared__ __align__(16) bf16 KV[2][STAGE_ELEMS];

    int blk = blockIdx.x;
    const bf16 *Qh, *Ql, *Kh, *Kl, *Vh, *Vl; float* O = nullptr;
    int NQ, NK, bh, q0, kt0, sp = 0;
    bool split;
    if (blk < 512) {   // dir1: y attends x, 4-way split-K
        split = true;
        bh = blk >> 6;
        int r2 = blk & 63;
        q0 = (r2 >> 2) * 64;
        sp = r2 & 3;
        kt0 = sp * 16;
        NQ = HWY; NK = HWX;
        Qh=g_qyh; Ql=g_qyl; Kh=g_kxh; Kl=g_kxl; Vh=g_vxh; Vl=g_vxl;
    } else {           // dir0: x attends y
        split = false;
        blk -= 512;
        bh = blk >> 6; q0 = (blk & 63) * 64; kt0 = 0; NQ = HWX; NK = HWY;
        Qh=g_qxh; Ql=g_qxl; Kh=g_kyh; Kl=g_kyl; Vh=g_vyh; Vl=g_vyl; O=g_ax;
    }
    const int nt = 16;

    const int tid = threadIdx.x, w = tid >> 5, lane = tid & 31;
    const size_t kbase = (size_t)bh * NK * HD;
    const size_t vbase = (size_t)bh * HD * NK;

    const int e0 = tid * 8, e1 = (tid + 128) * 8;
    const int ks0 = (e0 >> 5) * QSTR + (e0 & 31);
    const int ks1 = (e1 >> 5) * QSTR + (e1 & 31);
    const int vs0 = (e0 >> 6) * VSTR + (e0 & 63);
    const int vs1 = (e1 >> 6) * VSTR + (e1 & 63);
    const size_t kg0 = (size_t)(e0 >> 5) * HD + (e0 & 31);
    const size_t kg1 = (size_t)(e1 >> 5) * HD + (e1 & 31);
    const size_t vg0 = (size_t)(e0 >> 6) * NK + (e0 & 63);
    const size_t vg1 = (size_t)(e1 >> 6) * NK + (e1 & 63);

    unsigned sb0 = (unsigned)__cvta_generic_to_shared(&KV[0][0]);
    unsigned sb1 = (unsigned)__cvta_generic_to_shared(&KV[1][0]);

    {
        size_t ka = kbase + (size_t)kt0 * 64 * HD;
        size_t va = vbase + (size_t)kt0 * 64;
        cpasync16(sb0 + (OFF_KH + ks0) * 2, Kh + ka + kg0);
        cpasync16(sb0 + (OFF_KH + ks1) * 2, Kh + ka + kg1);
        cpasync16(sb0 + (OFF_KL + ks0) * 2, Kl + ka + kg0);
        cpasync16(sb0 + (OFF_KL + ks1) * 2, Kl + ka + kg1);
        cpasync16(sb0 + (OFF_VH + vs0) * 2, Vh + va + vg0);
        cpasync16(sb0 + (OFF_VH + vs1) * 2, Vh + va + vg1);
        cpasync16(sb0 + (OFF_VL + vs0) * 2, Vl + va + vg0);
        cpasync16(sb0 + (OFF_VL + vs1) * 2, Vl + va + vg1);
        asm volatile("cp.async.commit_group;");
    }

    {
        bf16* Qsh = &KV[1][0];
        bf16* Qsl = &KV[1][2560];
        const size_t qb = (size_t)bh * NQ * HD + (size_t)q0 * HD;
        #pragma unroll
        for (int it = 0; it < 2; it++) {
            int e = (tid + it * 128) * 8;
            int row = e >> 5, col = e & 31;
            *(uint4*)&Qsh[row * QSTR + col] = *(const uint4*)(Qh + qb + (size_t)row * HD + col);
            *(uint4*)&Qsl[row * QSTR + col] = *(const uint4*)(Ql + qb + (size_t)row * HD + col);
        }
    }
    __syncthreads();

    const int arow = (lane & 7) + ((lane & 8) ? 8 : 0);
    const int acol = (lane & 16) ? 8 : 0;
    const int brow = (lane & 7) + ((lane & 16) ? 8 : 0);
    const int bcol = (lane & 8) ? 8 : 0;
    unsigned qf[2][2][4];
    #pragma unroll
    for (int p = 0; p < 2; p++)
        #pragma unroll
        for (int c = 0; c < 2; c++)
            ldsm4(qf[p][c], &KV[1][p * 2560 + (w * 16 + arow) * QSTR + c * 16 + acol]);
    __syncthreads();

    float m0r = -1e30f, m1r = -1e30f, l0 = 0.f, l1 = 0.f;
    float oacc[4][4] = {};

    for (int i = 0; i < nt; i++) {
        const int s = i & 1;
        if (i + 1 < nt) {
            unsigned sb = (s ^ 1) ? sb1 : sb0;
            size_t ka = kbase + (size_t)(kt0 + i + 1) * 64 * HD;
            size_t va = vbase + (size_t)(kt0 + i + 1) * 64;
            cpasync16(sb + (OFF_KH + ks0) * 2, Kh + ka + kg0);
            cpasync16(sb + (OFF_KH + ks1) * 2, Kh + ka + kg1);
            cpasync16(sb + (OFF_KL + ks0) * 2, Kl + ka + kg0);
            cpasync16(sb + (OFF_KL + ks1) * 2, Kl + ka + kg1);
            cpasync16(sb + (OFF_VH + vs0) * 2, Vh + va + vg0);
            cpasync16(sb + (OFF_VH + vs1) * 2, Vh + va + vg1);
            cpasync16(sb + (OFF_VL + vs0) * 2, Vl + va + vg0);
            cpasync16(sb + (OFF_VL + vs1) * 2, Vl + va + vg1);
            asm volatile("cp.async.commit_group;");
            asm volatile("cp.async.wait_group 1;" ::: "memory");
        } else {
            asm volatile("cp.async.wait_group 0;" ::: "memory");
        }
        __syncthreads();

        const bf16* Ks0 = &KV[s][OFF_KH];
        const bf16* Ks1 = &KV[s][OFF_KL];
        const bf16* Vs0 = &KV[s][OFF_VH];
        const bf16* Vs1 = &KV[s][OFF_VL];

        float sreg[8][4];
        #pragma unroll
        for (int nb = 0; nb < 8; nb++)
            sreg[nb][0] = sreg[nb][1] = sreg[nb][2] = sreg[nb][3] = 0.f;

        #pragma unroll
        for (int c = 0; c < 2; c++) {
            #pragma unroll
            for (int jp = 0; jp < 4; jp++) {
                unsigned kh4[4], kl4[4];
                ldsm4(kh4, &Ks0[(jp * 16 + brow) * QSTR + c * 16 + bcol]);
                ldsm4(kl4, &Ks1[(jp * 16 + brow) * QSTR + c * 16 + bcol]);
                mma16816(sreg[2*jp],   qf[0][c], kh4[0], kh4[1]);
                mma16816(sreg[2*jp],   qf[1][c], kh4[0], kh4[1]);
                mma16816(sreg[2*jp],   qf[0][c], kl4[0], kl4[1]);
                mma16816(sreg[2*jp+1], qf[0][c], kh4[2], kh4[3]);
                mma16816(sreg[2*jp+1], qf[1][c], kh4[2], kh4[3]);
                mma16816(sreg[2*jp+1], qf[0][c], kl4[2], kl4[3]);
            }
        }

        float mx0 = sreg[0][0], mx1 = sreg[0][2];
        #pragma unroll
        for (int nb = 0; nb < 8; nb++) {
            mx0 = fmaxf(mx0, fmaxf(sreg[nb][0], sreg[nb][1]));
            mx1 = fmaxf(mx1, fmaxf(sreg[nb][2], sreg[nb][3]));
        }
        mx0 = fmaxf(mx0, __shfl_xor_sync(~0u, mx0, 1));
        mx0 = fmaxf(mx0, __shfl_xor_sync(~0u, mx0, 2));
        mx1 = fmaxf(mx1, __shfl_xor_sync(~0u, mx1, 1));
        mx1 = fmaxf(mx1, __shfl_xor_sync(~0u, mx1, 2));
        float nm0 = fmaxf(m0r, mx0), nm1 = fmaxf(m1r, mx1);
        float sc0 = exp2f(m0r - nm0), sc1 = exp2f(m1r - nm1);
        m0r = nm0; m1r = nm1;
        float rs0 = 0.f, rs1 = 0.f;
        #pragma unroll
        for (int nb = 0; nb < 8; nb++) {
            sreg[nb][0] = exp2f(sreg[nb][0] - nm0);
            sreg[nb][1] = exp2f(sreg[nb][1] - nm0);
            sreg[nb][2] = exp2f(sreg[nb][2] - nm1);
            sreg[nb][3] = exp2f(sreg[nb][3] - nm1);
            rs0 += sreg[nb][0] + sreg[nb][1];
            rs1 += sreg[nb][2] + sreg[nb][3];
        }
        rs0 += __shfl_xor_sync(~0u, rs0, 1);
        rs0 += __shfl_xor_sync(~0u, rs0, 2);
        rs1 += __shfl_xor_sync(~0u, rs1, 1);
        rs1 += __shfl_xor_sync(~0u, rs1, 2);
        l0 = l0 * sc0 + rs0;  l1 = l1 * sc1 + rs1;
        #pragma unroll
        for (int nb = 0; nb < 4; nb++) {
            oacc[nb][0] *= sc0; oacc[nb][1] *= sc0;
            oacc[nb][2] *= sc1; oacc[nb][3] *= sc1;
        }

        #pragma unroll
        for (int c = 0; c < 4; c++) {
            unsigned pah[4], pal[4];
            #pragma unroll
            for (int r4 = 0; r4 < 4; r4++) {
                int nb = 2 * c + (r4 >> 1);
                int pr = (r4 & 1) * 2;
                psplit2(sreg[nb][pr], sreg[nb][pr + 1], pah[r4], pal[r4]);
            }
            #pragma unroll
            for (int np = 0; np < 2; np++) {
                unsigned vh4[4], vl4[4];
                ldsm4(vh4, &Vs0[(np * 16 + brow) * VSTR + c * 16 + bcol]);
                ldsm4(vl4, &Vs1[(np * 16 + brow) * VSTR + c * 16 + bcol]);
                mma16816(oacc[2*np],   pah, vh4[0], vh4[1]);
                mma16816(oacc[2*np],   pal, vh4[0], vh4[1]);
                mma16816(oacc[2*np],   pah, vl4[0], vl4[1]);
                mma16816(oacc[2*np+1], pah, vh4[2], vh4[3]);
                mma16816(oacc[2*np+1], pal, vh4[2], vh4[3]);
                mma16816(oacc[2*np+1], pah, vl4[2], vl4[3]);
            }
        }
        __syncthreads();
    }

    int r = lane >> 2;
    int qg = q0 + w * 16 + r;
    if (split) {
        size_t pb = ((size_t)sp * 8 + bh) * HWY;
        #pragma unroll
        for (int nb = 0; nb < 4; nb++) {
            int d = nb * 8 + (lane & 3) * 2;
            *(float2*)&g_pacc[(pb + qg) * HD + d]     = make_float2(oacc[nb][0], oacc[nb][1]);
            *(float2*)&g_pacc[(pb + qg + 8) * HD + d] = make_float2(oacc[nb][2], oacc[nb][3]);
        }
        if ((lane & 3) == 0) {
            g_pml[pb + qg]     = make_float2(m0r, l0);
            g_pml[pb + qg + 8] = make_float2(m1r, l1);
        }
    } else {
        float inv0 = 1.f / l0, inv1 = 1.f / l1;
        size_t ob = (size_t)bh * NQ * HD;
        #pragma unroll
        for (int nb = 0; nb < 4; nb++) {
            int d = nb * 8 + (lane & 3) * 2;
            float2 v0 = make_float2(oacc[nb][0] * inv0, oacc[nb][1] * inv0);
            float2 v1 = make_float2(oacc[nb][2] * inv1, oacc[nb][3] * inv1);
            *(float2*)&O[ob + (size_t)qg * HD + d]       = v0;
            *(float2*)&O[ob + (size_t)(qg + 8) * HD + d] = v1;
        }
    }
}

// ====== combine split-K partials for dir1 (validated round-12) =============
__global__ void __launch_bounds__(128) attn_combine_kernel()
{
    int t = blockIdx.x * 128 + threadIdx.x;
    int bh = t >> 10, q = t & 1023;
    float2 ml[4];
    float M = -1e30f;
    #pragma unroll
    for (int s = 0; s < 4; s++) {
        ml[s] = g_pml[((size_t)s * 8 + bh) * HWY + q];
        M = fmaxf(M, ml[s].x);
    }
    float wgt[4], L = 0.f;
    #pragma unroll
    for (int s = 0; s < 4; s++) {
        wgt[s] = exp2f(ml[s].x - M);
        L += wgt[s] * ml[s].y;
    }
    float invL = 1.f / L;
    float* dst = g_ay + ((size_t)bh * HWY + q) * HD;
    #pragma unroll
    for (int d = 0; d < HD; d += 4) {
        float4 o = make_float4(0.f, 0.f, 0.f, 0.f);
        #pragma unroll
        for (int s = 0; s < 4; s++) {
            const float* a = g_pacc + (((size_t)s * 8 + bh) * HWY + q) * HD;
            float4 v = *(const float4*)(a + d);
            o.x += wgt[s] * v.x;  o.y += wgt[s] * v.y;
            o.z += wgt[s] * v.z;  o.w += wgt[s] * v.w;
        }
        o.x *= invL; o.y *= invL; o.z *= invL; o.w *= invL;
        *(float4*)(dst + d) = o;
    }
}

// ============================== launcher ==================================
extern "C" void kernel_launch(void* const* d_in, const int* in_sizes, int n_in,
                              void* d_out, int out_size)
{
    (void)out_size;
    const float *x=0, *y=0, *wxq=0, *bxq=0, *wyq=0, *byq=0,
                *wpx=0, *bpx=0, *wpy=0, *bpy=0;
    for (int i = 0; i < n_in; i++) {
        const float* p = (const float*)d_in[i];
        switch (in_sizes[i]) {
            case 2097152: x = p;   break;
            case 1048576: y = p;   break;
            case 98304:   wxq = p; break;
            case 196608:  wyq = p; break;
            case 32768:   wpx = p; break;
            case 65536:   wpy = p; break;
            case 256:     bpx = p; break;
            case 512:     bpy = p; break;
            case 384:     if (!bxq) bxq = p; else byq = p; break;
            default: break;
        }
    }
    float* out = (float*)d_out;

    split_w_kernel<<<288, 256>>>(wxq, wyq);
    presplit_x_kernel<<<3072, 256>>>(x, y);
    qkv_mma5_kernel<<<480, 256>>>(bxq, byq);
    attn_mma_kernel<<<1024, 128>>>();
    attn_combine_kernel<<<64, 128>>>();
    gemm_proj_kernel<<<768, 256>>>(wpx, bpx, x, wpy, bpy, y, out);
}

// round 14
// speedup vs baseline: 1.3868x; 1.0698x over previous
#include <cuda_runtime.h>
#include <cuda_bf16.h>

#define X_CH   256
#define Y_CH   512
#define DIM    128
#define NHEAD  4
#define HD     32
#define HWX    4096
#define HWY    1024
#define BATCH  2
#define GAMMA  0.17677669529663687f
#define GAMMA_L2E (0.17677669529663687f * 1.4426950408889634f)

typedef __nv_bfloat16 bf16;

// ---------------- scratch (device globals; no allocation) ----------------
static __device__ __align__(16) bf16 g_qxh[BATCH*NHEAD*HWX*HD], g_qxl[BATCH*NHEAD*HWX*HD];
static __device__ __align__(16) bf16 g_kxh[BATCH*NHEAD*HWX*HD], g_kxl[BATCH*NHEAD*HWX*HD];
static __device__ __align__(16) bf16 g_vxh[BATCH*NHEAD*HWX*HD], g_vxl[BATCH*NHEAD*HWX*HD];
static __device__ __align__(16) bf16 g_qyh[BATCH*NHEAD*HWY*HD], g_qyl[BATCH*NHEAD*HWY*HD];
static __device__ __align__(16) bf16 g_kyh[BATCH*NHEAD*HWY*HD], g_kyl[BATCH*NHEAD*HWY*HD];
static __device__ __align__(16) bf16 g_vyh[BATCH*NHEAD*HWY*HD], g_vyl[BATCH*NHEAD*HWY*HD];
// attention out, split bf16, TRANSPOSED [b, c=h*32+d, q]
static __device__ __align__(16) bf16 g_axh[BATCH*DIM*HWX], g_axl[BATCH*DIM*HWX];
static __device__ __align__(16) bf16 g_ayh[BATCH*DIM*HWY], g_ayl[BATCH*DIM*HWY];
// pre-split weights [M][K] and inputs [B][C][N]
static __device__ __align__(16) bf16 g_wxqh[384*X_CH], g_wxql[384*X_CH];
static __device__ __align__(16) bf16 g_wyqh[384*Y_CH], g_wyql[384*Y_CH];
static __device__ __align__(16) bf16 g_wpxh[X_CH*DIM], g_wpxl[X_CH*DIM];
static __device__ __align__(16) bf16 g_wpyh[Y_CH*DIM], g_wpyl[Y_CH*DIM];
static __device__ __align__(16) bf16 g_xsh[BATCH*X_CH*HWX], g_xsl[BATCH*X_CH*HWX];
static __device__ __align__(16) bf16 g_ysh[BATCH*Y_CH*HWY], g_ysl[BATCH*Y_CH*HWY];
// split-K partials for dir1
static __device__ __align__(16) float  g_pacc[4*BATCH*NHEAD*HWY*HD];
static __device__ __align__(16) float2 g_pml[4*BATCH*NHEAD*HWY];

__device__ __forceinline__ void bsplit(float v, bf16& h, bf16& l) {
    h = __float2bfloat16(v);
    l = __float2bfloat16(v - __bfloat162float(h));
}
__device__ __forceinline__ unsigned pack2(bf16 a, bf16 b) {
    return (unsigned)__bfloat16_as_ushort(a) | ((unsigned)__bfloat16_as_ushort(b) << 16);
}
__device__ __forceinline__ void psplit2(float x0, float x1, unsigned& ph, unsigned& pl) {
    unsigned h;
    asm("cvt.rn.bf16x2.f32 %0, %1, %2;" : "=r"(h) : "f"(x1), "f"(x0));
    float h0 = __uint_as_float(h << 16);
    float h1 = __uint_as_float(h & 0xffff0000u);
    float e0 = x0 - h0, e1 = x1 - h1;
    asm("cvt.rn.bf16x2.f32 %0, %1, %2;" : "=r"(pl) : "f"(e1), "f"(e0));
    ph = h;
}

// ---------------- prep: split all 4 weight matrices (elementwise) ---------
__global__ void __launch_bounds__(256) split_w_kernel(
    const float* __restrict__ s0, const float* __restrict__ s1,
    const float* __restrict__ s2, const float* __restrict__ s3)
{
    int e = (blockIdx.x * 256 + threadIdx.x) * 4;
    const float* s; bf16 *dh, *dl;
    if (e < 98304)       { s = s0; dh = g_wxqh; dl = g_wxql; }
    else if (e < 294912) { e -= 98304;  s = s1; dh = g_wyqh; dl = g_wyql; }
    else if (e < 327680) { e -= 294912; s = s2; dh = g_wpxh; dl = g_wpxl; }
    else                 { e -= 327680; s = s3; dh = g_wpyh; dl = g_wpyl; }
    float4 v = *(const float4*)(s + e);
    bf16 h0,l0,h1,l1,h2,l2,h3,l3;
    bsplit(v.x,h0,l0); bsplit(v.y,h1,l1); bsplit(v.z,h2,l2); bsplit(v.w,h3,l3);
    *(uint2*)(dh + e) = make_uint2(pack2(h0,h1), pack2(h2,h3));
    *(uint2*)(dl + e) = make_uint2(pack2(l0,l1), pack2(l2,l3));
}

// ---------------- prep: split inputs elementwise (validated) ----------
__global__ void __launch_bounds__(256) presplit_x_kernel(
    const float* __restrict__ x, const float* __restrict__ y)
{
    int e = (blockIdx.x * 256 + threadIdx.x) * 4;
    const float* s; bf16 *dh, *dl;
    if (e < BATCH*X_CH*HWX) { s = x; dh = g_xsh; dl = g_xsl; }
    else { e -= BATCH*X_CH*HWX; s = y; dh = g_ysh; dl = g_ysl; }
    float4 v = *(const float4*)(s + e);
    bf16 h0,l0,h1,l1,h2,l2,h3,l3;
    bsplit(v.x,h0,l0); bsplit(v.y,h1,l1); bsplit(v.z,h2,l2); bsplit(v.w,h3,l3);
    *(uint2*)(dh + e) = make_uint2(pack2(h0,h1), pack2(h2,h3));
    *(uint2*)(dl + e) = make_uint2(pack2(l0,l1), pack2(l2,l3));
}

// ---------------- MMA helpers ----------------
__device__ __forceinline__ void ldsm4(unsigned r[4], const void* p) {
    unsigned a = (unsigned)__cvta_generic_to_shared(p);
    asm volatile("ldmatrix.sync.aligned.m8n8.x4.shared.b16 {%0,%1,%2,%3}, [%4];"
        : "=r"(r[0]), "=r"(r[1]), "=r"(r[2]), "=r"(r[3]) : "r"(a));
}
__device__ __forceinline__ void ldsm4t(unsigned r[4], const void* p) {
    unsigned a = (unsigned)__cvta_generic_to_shared(p);
    asm volatile("ldmatrix.sync.aligned.m8n8.x4.trans.shared.b16 {%0,%1,%2,%3}, [%4];"
        : "=r"(r[0]), "=r"(r[1]), "=r"(r[2]), "=r"(r[3]) : "r"(a));
}
__device__ __forceinline__ void mma16816(float c[4], const unsigned a[4],
                                         unsigned b0, unsigned b1) {
    asm volatile("mma.sync.aligned.m16n8k16.row.col.f32.bf16.bf16.f32 "
        "{%0,%1,%2,%3}, {%4,%5,%6,%7}, {%8,%9}, {%0,%1,%2,%3};"
        : "+f"(c[0]), "+f"(c[1]), "+f"(c[2]), "+f"(c[3])
        : "r"(a[0]), "r"(a[1]), "r"(a[2]), "r"(a[3]), "r"(b0), "r"(b1));
}
__device__ __forceinline__ void cpasync16(unsigned dst, const void* src) {
    asm volatile("cp.async.ca.shared.global [%0], [%1], 16;" :: "r"(dst), "l"(src));
}

// ====== shared GEMM geometry (v5 template, validated round-13) ============
#define ASTR 24
#define BSTR5 72
#define ST_A 3072
#define ST_B5 1152
#define ST_TOT5 8448

// ====== QKV tensor-core GEMM v5 (validated round-13) ======================
__global__ void __launch_bounds__(256) qkv_mma5_kernel(
    const float* __restrict__ bx, const float* __restrict__ by_)
{
    __shared__ __align__(16) char SMB[33792];
    bf16* SM = (bf16*)SMB;
    float* Cst = (float*)SMB;

    const bf16 *Wh, *Wl, *Xh, *Xl;
    const float* bias;
    bf16 *Qh_, *Ql_, *Kh_, *Kl_, *Vh_, *Vl_;
    int N, K, m0, n0, b;
    int blk = blockIdx.x;
    if (blk < 96) {
        N = HWY; K = Y_CH;
        b = blk / 48; int r = blk % 48; m0 = (r % 3) * 128; n0 = (r / 3) * 64;
        Wh = g_wyqh; Wl = g_wyql;
        Xh = g_ysh + (size_t)b * K * N; Xl = g_ysl + (size_t)b * K * N;
        bias = by_;
        Qh_=g_qyh; Ql_=g_qyl; Kh_=g_kyh; Kl_=g_kyl; Vh_=g_vyh; Vl_=g_vyl;
    } else {
        blk -= 96;
        N = HWX; K = X_CH;
        b = blk / 192; int r = blk % 192; m0 = (r % 3) * 128; n0 = (r / 3) * 64;
        Wh = g_wxqh; Wl = g_wxql;
        Xh = g_xsh + (size_t)b * K * N; Xl = g_xsl + (size_t)b * K * N;
        bias = bx;
        Qh_=g_qxh; Ql_=g_qxl; Kh_=g_kxh; Kl_=g_kxl; Vh_=g_vxh; Vl_=g_vxl;
    }

    const int tid = threadIdx.x, lane = tid & 31;
    const int w = tid >> 5;
    const int wm = w & 3, wn = w >> 2;
    const int arow = (lane & 7) + ((lane & 8) ? 8 : 0);
    const int acol = (lane & 16) ? 8 : 0;
    const int bkrow = (lane & 7) + ((lane & 8) ? 8 : 0);
    const int bncol = (lane & 16) ? 8 : 0;

    const unsigned sbase = (unsigned)__cvta_generic_to_shared(SMB);

    auto fill = [&](int s, int kc) {
        #pragma unroll
        for (int it = 0; it < 3; it++) {
            int id = tid + it * 256;
            if (id < 512) {
                int part = id & 1, rid = id >> 1;
                int row = rid >> 1, cc = rid & 1;
                unsigned adst = sbase + (unsigned)(s*ST_TOT5 + part*ST_A + row*ASTR + cc*8) * 2;
                cpasync16(adst, (part ? Wl : Wh) + (size_t)(m0 + row) * K + kc*16 + cc*8);
            } else {
                int j = id - 512;
                int part = j & 1, rid2 = j >> 1;
                int krow = rid2 >> 3, nc = rid2 & 7;
                unsigned bdst = sbase + (unsigned)(s*ST_TOT5 + 2*ST_A + part*ST_B5 + krow*BSTR5 + nc*8) * 2;
                cpasync16(bdst, (part ? Xl : Xh) + (size_t)(kc*16 + krow) * N + n0 + nc*8);
            }
        }
        asm volatile("cp.async.commit_group;");
    };

    float acc[2][4][4] = {};
    const int nkc = K >> 4;

    fill(0, 0);
    for (int kc = 0; kc < nkc; kc++) {
        const int s = kc & 1;
        if (kc + 1 < nkc) {
            fill(s ^ 1, kc + 1);
            asm volatile("cp.async.wait_group 1;" ::: "memory");
        } else {
            asm volatile("cp.async.wait_group 0;" ::: "memory");
        }
        __syncthreads();

        const bf16* Ah = SM + s*ST_TOT5;
        const bf16* Al = Ah + ST_A;
        const bf16* Bh = SM + s*ST_TOT5 + 2*ST_A;
        const bf16* Bl = Bh + ST_B5;

        unsigned ah[2][4], al[2][4];
        #pragma unroll
        for (int im = 0; im < 2; im++) {
            ldsm4(ah[im], &Ah[(wm*32 + im*16 + arow) * ASTR + acol]);
            ldsm4(al[im], &Al[(wm*32 + im*16 + arow) * ASTR + acol]);
        }
        #pragma unroll
        for (int jn = 0; jn < 2; jn++) {
            unsigned bh4[4], bl4[4];
            const int boff = bkrow * BSTR5 + wn*32 + jn*16 + bncol;
            ldsm4t(bh4, &Bh[boff]);
            ldsm4t(bl4, &Bl[boff]);
            #pragma unroll
            for (int im = 0; im < 2; im++) {
                mma16816(acc[im][2*jn],   ah[im], bh4[0], bh4[1]);
                mma16816(acc[im][2*jn],   al[im], bh4[0], bh4[1]);
                mma16816(acc[im][2*jn],   ah[im], bl4[0], bl4[1]);
                mma16816(acc[im][2*jn+1], ah[im], bh4[2], bh4[3]);
                mma16816(acc[im][2*jn+1], al[im], bh4[2], bh4[3]);
                mma16816(acc[im][2*jn+1], ah[im], bl4[2], bl4[3]);
            }
        }
        __syncthreads();
    }

    const int r = lane >> 2, cq = (lane & 3) * 2;
    #pragma unroll
    for (int im = 0; im < 2; im++) {
        __syncthreads();
        #pragma unroll
        for (int j8 = 0; j8 < 4; j8++) {
            int col = wn*32 + j8*8 + cq;
            Cst[(wm*16 + r) * 64 + col]         = acc[im][j8][0];
            Cst[(wm*16 + r) * 64 + col + 1]     = acc[im][j8][1];
            Cst[(wm*16 + r + 8) * 64 + col]     = acc[im][j8][2];
            Cst[(wm*16 + r + 8) * 64 + col + 1] = acc[im][j8][3];
        }
        __syncthreads();
        for (int idx = tid; idx < 64*64; idx += 256) {
            int srow = idx >> 6, scol = idx & 63;
            int o = m0 + (srow >> 4) * 32 + im*16 + (srow & 15);
            int n = n0 + scol;
            float v = Cst[idx] + bias[o];
            int t = o >> 7, h = (o & 127) >> 5, d = o & 31;
            bf16 hh, ll;
            if (t == 0) {
                bsplit(v * GAMMA_L2E, hh, ll);
                size_t i2 = ((size_t)(b*NHEAD + h) * N + n) * HD + d;
                Qh_[i2] = hh;  Ql_[i2] = ll;
            } else if (t == 1) {
                bsplit(v, hh, ll);
                size_t i2 = ((size_t)(b*NHEAD + h) * N + n) * HD + d;
                Kh_[i2] = hh;  Kl_[i2] = ll;
            } else {
                bsplit(v, hh, ll);
                size_t i2 = ((size_t)(b*NHEAD + h) * HD + d) * N + n;
                Vh_[i2] = hh;  Vl_[i2] = ll;
            }
        }
    }
}

// ====== proj tensor-core GEMM (v5 template, K=128) =========================
// B = attention output split bf16, [b][c=h*32+d][q] layout.
// blocks [0,128): y (2b x 4m x 16n); [128,384): x (2b x 2m x 64n).
__global__ void __launch_bounds__(256) proj_mma_kernel(
    const float* __restrict__ bpx, const float* __restrict__ Rx,
    const float* __restrict__ bpy, const float* __restrict__ Ry,
    float* __restrict__ outp)
{
    __shared__ __align__(16) char SMB[33792];
    bf16* SM = (bf16*)SMB;
    float* Cst = (float*)SMB;

    const bf16 *Wh, *Wl, *Xh, *Xl;
    const float *bias, *Res;
    float* Out;
    int N, OC, m0, n0, b;
    int blk = blockIdx.x;
    if (blk < 128) {
        N = HWY; OC = Y_CH;
        b = blk / 64; int r = blk % 64; m0 = (r % 4) * 128; n0 = (r / 4) * 64;
        Wh = g_wpyh; Wl = g_wpyl;
        Xh = g_ayh + (size_t)b * DIM * N; Xl = g_ayl + (size_t)b * DIM * N;
        bias = bpy; Res = Ry; Out = outp + (size_t)BATCH * X_CH * HWX;
    } else {
        blk -= 128;
        N = HWX; OC = X_CH;
        b = blk / 128; int r = blk % 128; m0 = (r % 2) * 128; n0 = (r / 2) * 64;
        Wh = g_wpxh; Wl = g_wpxl;
        Xh = g_axh + (size_t)b * DIM * N; Xl = g_axl + (size_t)b * DIM * N;
        bias = bpx; Res = Rx; Out = outp;
    }
    const int K = DIM;

    const int tid = threadIdx.x, lane = tid & 31;
    const int w = tid >> 5;
    const int wm = w & 3, wn = w >> 2;
    const int arow = (lane & 7) + ((lane & 8) ? 8 : 0);
    const int acol = (lane & 16) ? 8 : 0;
    const int bkrow = (lane & 7) + ((lane & 8) ? 8 : 0);
    const int bncol = (lane & 16) ? 8 : 0;

    const unsigned sbase = (unsigned)__cvta_generic_to_shared(SMB);

    auto fill = [&](int s, int kc) {
        #pragma unroll
        for (int it = 0; it < 3; it++) {
            int id = tid + it * 256;
            if (id < 512) {
                int part = id & 1, rid = id >> 1;
                int row = rid >> 1, cc = rid & 1;
                unsigned adst = sbase + (unsigned)(s*ST_TOT5 + part*ST_A + row*ASTR + cc*8) * 2;
                cpasync16(adst, (part ? Wl : Wh) + (size_t)(m0 + row) * K + kc*16 + cc*8);
            } else {
                int j = id - 512;
                int part = j & 1, rid2 = j >> 1;
                int krow = rid2 >> 3, nc = rid2 & 7;
                unsigned bdst = sbase + (unsigned)(s*ST_TOT5 + 2*ST_A + part*ST_B5 + krow*BSTR5 + nc*8) * 2;
                cpasync16(bdst, (part ? Xl : Xh) + (size_t)(kc*16 + krow) * N + n0 + nc*8);
            }
        }
        asm volatile("cp.async.commit_group;");
    };

    float acc[2][4][4] = {};
    const int nkc = K >> 4;   // 8

    fill(0, 0);
    for (int kc = 0; kc < nkc; kc++) {
        const int s = kc & 1;
        if (kc + 1 < nkc) {
            fill(s ^ 1, kc + 1);
            asm volatile("cp.async.wait_group 1;" ::: "memory");
        } else {
            asm volatile("cp.async.wait_group 0;" ::: "memory");
        }
        __syncthreads();

        const bf16* Ah = SM + s*ST_TOT5;
        const bf16* Al = Ah + ST_A;
        const bf16* Bh = SM + s*ST_TOT5 + 2*ST_A;
        const bf16* Bl = Bh + ST_B5;

        unsigned ah[2][4], al[2][4];
        #pragma unroll
        for (int im = 0; im < 2; im++) {
            ldsm4(ah[im], &Ah[(wm*32 + im*16 + arow) * ASTR + acol]);
            ldsm4(al[im], &Al[(wm*32 + im*16 + arow) * ASTR + acol]);
        }
        #pragma unroll
        for (int jn = 0; jn < 2; jn++) {
            unsigned bh4[4], bl4[4];
            const int boff = bkrow * BSTR5 + wn*32 + jn*16 + bncol;
            ldsm4t(bh4, &Bh[boff]);
            ldsm4t(bl4, &Bl[boff]);
            #pragma unroll
            for (int im = 0; im < 2; im++) {
                mma16816(acc[im][2*jn],   ah[im], bh4[0], bh4[1]);
                mma16816(acc[im][2*jn],   al[im], bh4[0], bh4[1]);
                mma16816(acc[im][2*jn],   ah[im], bl4[0], bl4[1]);
                mma16816(acc[im][2*jn+1], ah[im], bh4[2], bh4[3]);
                mma16816(acc[im][2*jn+1], al[im], bh4[2], bh4[3]);
                mma16816(acc[im][2*jn+1], ah[im], bl4[2], bl4[3]);
            }
        }
        __syncthreads();
    }

    // epilogue: staged -> fp32 out = acc + bias + residual (coalesced)
    const int r = lane >> 2, cq = (lane & 3) * 2;
    #pragma unroll
    for (int im = 0; im < 2; im++) {
        __syncthreads();
        #pragma unroll
        for (int j8 = 0; j8 < 4; j8++) {
            int col = wn*32 + j8*8 + cq;
            Cst[(wm*16 + r) * 64 + col]         = acc[im][j8][0];
            Cst[(wm*16 + r) * 64 + col + 1]     = acc[im][j8][1];
            Cst[(wm*16 + r + 8) * 64 + col]     = acc[im][j8][2];
            Cst[(wm*16 + r + 8) * 64 + col + 1] = acc[im][j8][3];
        }
        __syncthreads();
        for (int idx = tid; idx < 64*64; idx += 256) {
            int srow = idx >> 6, scol = idx & 63;
            int o = m0 + (srow >> 4) * 32 + im*16 + (srow & 15);
            int n = n0 + scol;
            size_t off = ((size_t)b * OC + o) * N + n;
            Out[off] = Cst[idx] + bias[o] + Res[off];
        }
    }
}

// ====== MMA flash attention: split-K dir1 (validated), split-bf16-T out ====
#define QSTR 40
#define VSTR 72
#define OFF_KH 0
#define OFF_KL 2560
#define OFF_VH 5120
#define OFF_VL 7424
#define STAGE_ELEMS 9728

__global__ void __launch_bounds__(128) attn_mma_kernel()
{
    __shared__ __align__(16) bf16 KV[2][STAGE_ELEMS];

    int blk = blockIdx.x;
    const bf16 *Qh, *Ql, *Kh, *Kl, *Vh, *Vl;
    bf16 *Oh_ = nullptr, *Ol_ = nullptr;
    int NQ, NK, bh, q0, kt0, sp = 0;
    bool split;
    if (blk < 512) {   // dir1: y attends x, 4-way split-K
        split = true;
        bh = blk >> 6;
        int r2 = blk & 63;
        q0 = (r2 >> 2) * 64;
        sp = r2 & 3;
        kt0 = sp * 16;
        NQ = HWY; NK = HWX;
        Qh=g_qyh; Ql=g_qyl; Kh=g_kxh; Kl=g_kxl; Vh=g_vxh; Vl=g_vxl;
    } else {           // dir0: x attends y
        split = false;
        blk -= 512;
        bh = blk >> 6; q0 = (blk & 63) * 64; kt0 = 0; NQ = HWX; NK = HWY;
        Qh=g_qxh; Ql=g_qxl; Kh=g_kyh; Kl=g_kyl; Vh=g_vyh; Vl=g_vyl;
        Oh_ = g_axh; Ol_ = g_axl;
    }
    const int nt = 16;

    const int tid = threadIdx.x, w = tid >> 5, lane = tid & 31;
    const size_t kbase = (size_t)bh * NK * HD;
    const size_t vbase = (size_t)bh * HD * NK;

    const int e0 = tid * 8, e1 = (tid + 128) * 8;
    const int ks0 = (e0 >> 5) * QSTR + (e0 & 31);
    const int ks1 = (e1 >> 5) * QSTR + (e1 & 31);
    const int vs0 = (e0 >> 6) * VSTR + (e0 & 63);
    const int vs1 = (e1 >> 6) * VSTR + (e1 & 63);
    const size_t kg0 = (size_t)(e0 >> 5) * HD + (e0 & 31);
    const size_t kg1 = (size_t)(e1 >> 5) * HD + (e1 & 31);
    const size_t vg0 = (size_t)(e0 >> 6) * NK + (e0 & 63);
    const size_t vg1 = (size_t)(e1 >> 6) * NK + (e1 & 63);

    unsigned sb0 = (unsigned)__cvta_generic_to_shared(&KV[0][0]);
    unsigned sb1 = (unsigned)__cvta_generic_to_shared(&KV[1][0]);

    {
        size_t ka = kbase + (size_t)kt0 * 64 * HD;
        size_t va = vbase + (size_t)kt0 * 64;
        cpasync16(sb0 + (OFF_KH + ks0) * 2, Kh + ka + kg0);
        cpasync16(sb0 + (OFF_KH + ks1) * 2, Kh + ka + kg1);
        cpasync16(sb0 + (OFF_KL + ks0) * 2, Kl + ka + kg0);
        cpasync16(sb0 + (OFF_KL + ks1) * 2, Kl + ka + kg1);
        cpasync16(sb0 + (OFF_VH + vs0) * 2, Vh + va + vg0);
        cpasync16(sb0 + (OFF_VH + vs1) * 2, Vh + va + vg1);
        cpasync16(sb0 + (OFF_VL + vs0) * 2, Vl + va + vg0);
        cpasync16(sb0 + (OFF_VL + vs1) * 2, Vl + va + vg1);
        asm volatile("cp.async.commit_group;");
    }

    {
        bf16* Qsh = &KV[1][0];
        bf16* Qsl = &KV[1][2560];
        const size_t qb = (size_t)bh * NQ * HD + (size_t)q0 * HD;
        #pragma unroll
        for (int it = 0; it < 2; it++) {
            int e = (tid + it * 128) * 8;
            int row = e >> 5, col = e & 31;
            *(uint4*)&Qsh[row * QSTR + col] = *(const uint4*)(Qh + qb + (size_t)row * HD + col);
            *(uint4*)&Qsl[row * QSTR + col] = *(const uint4*)(Ql + qb + (size_t)row * HD + col);
        }
    }
    __syncthreads();

    const int arow = (lane & 7) + ((lane & 8) ? 8 : 0);
    const int acol = (lane & 16) ? 8 : 0;
    const int brow = (lane & 7) + ((lane & 16) ? 8 : 0);
    const int bcol = (lane & 8) ? 8 : 0;
    unsigned qf[2][2][4];
    #pragma unroll
    for (int p = 0; p < 2; p++)
        #pragma unroll
        for (int c = 0; c < 2; c++)
            ldsm4(qf[p][c], &KV[1][p * 2560 + (w * 16 + arow) * QSTR + c * 16 + acol]);
    __syncthreads();

    float m0r = -1e30f, m1r = -1e30f, l0 = 0.f, l1 = 0.f;
    float oacc[4][4] = {};

    for (int i = 0; i < nt; i++) {
        const int s = i & 1;
        if (i + 1 < nt) {
            unsigned sb = (s ^ 1) ? sb1 : sb0;
            size_t ka = kbase + (size_t)(kt0 + i + 1) * 64 * HD;
            size_t va = vbase + (size_t)(kt0 + i + 1) * 64;
            cpasync16(sb + (OFF_KH + ks0) * 2, Kh + ka + kg0);
            cpasync16(sb + (OFF_KH + ks1) * 2, Kh + ka + kg1);
            cpasync16(sb + (OFF_KL + ks0) * 2, Kl + ka + kg0);
            cpasync16(sb + (OFF_KL + ks1) * 2, Kl + ka + kg1);
            cpasync16(sb + (OFF_VH + vs0) * 2, Vh + va + vg0);
            cpasync16(sb + (OFF_VH + vs1) * 2, Vh + va + vg1);
            cpasync16(sb + (OFF_VL + vs0) * 2, Vl + va + vg0);
            cpasync16(sb + (OFF_VL + vs1) * 2, Vl + va + vg1);
            asm volatile("cp.async.commit_group;");
            asm volatile("cp.async.wait_group 1;" ::: "memory");
        } else {
            asm volatile("cp.async.wait_group 0;" ::: "memory");
        }
        __syncthreads();

        const bf16* Ks0 = &KV[s][OFF_KH];
        const bf16* Ks1 = &KV[s][OFF_KL];
        const bf16* Vs0 = &KV[s][OFF_VH];
        const bf16* Vs1 = &KV[s][OFF_VL];

        float sreg[8][4];
        #pragma unroll
        for (int nb = 0; nb < 8; nb++)
            sreg[nb][0] = sreg[nb][1] = sreg[nb][2] = sreg[nb][3] = 0.f;

        #pragma unroll
        for (int c = 0; c < 2; c++) {
            #pragma unroll
            for (int jp = 0; jp < 4; jp++) {
                unsigned kh4[4], kl4[4];
                ldsm4(kh4, &Ks0[(jp * 16 + brow) * QSTR + c * 16 + bcol]);
                ldsm4(kl4, &Ks1[(jp * 16 + brow) * QSTR + c * 16 + bcol]);
                mma16816(sreg[2*jp],   qf[0][c], kh4[0], kh4[1]);
                mma16816(sreg[2*jp],   qf[1][c], kh4[0], kh4[1]);
                mma16816(sreg[2*jp],   qf[0][c], kl4[0], kl4[1]);
                mma16816(sreg[2*jp+1], qf[0][c], kh4[2], kh4[3]);
                mma16816(sreg[2*jp+1], qf[1][c], kh4[2], kh4[3]);
                mma16816(sreg[2*jp+1], qf[0][c], kl4[2], kl4[3]);
            }
        }

        float mx0 = sreg[0][0], mx1 = sreg[0][2];
        #pragma unroll
        for (int nb = 0; nb < 8; nb++) {
            mx0 = fmaxf(mx0, fmaxf(sreg[nb][0], sreg[nb][1]));
            mx1 = fmaxf(mx1, fmaxf(sreg[nb][2], sreg[nb][3]));
        }
        mx0 = fmaxf(mx0, __shfl_xor_sync(~0u, mx0, 1));
        mx0 = fmaxf(mx0, __shfl_xor_sync(~0u, mx0, 2));
        mx1 = fmaxf(mx1, __shfl_xor_sync(~0u, mx1, 1));
        mx1 = fmaxf(mx1, __shfl_xor_sync(~0u, mx1, 2));
        float nm0 = fmaxf(m0r, mx0), nm1 = fmaxf(m1r, mx1);
        float sc0 = exp2f(m0r - nm0), sc1 = exp2f(m1r - nm1);
        m0r = nm0; m1r = nm1;
        float rs0 = 0.f, rs1 = 0.f;
        #pragma unroll
        for (int nb = 0; nb < 8; nb++) {
            sreg[nb][0] = exp2f(sreg[nb][0] - nm0);
            sreg[nb][1] = exp2f(sreg[nb][1] - nm0);
            sreg[nb][2] = exp2f(sreg[nb][2] - nm1);
            sreg[nb][3] = exp2f(sreg[nb][3] - nm1);
            rs0 += sreg[nb][0] + sreg[nb][1];
            rs1 += sreg[nb][2] + sreg[nb][3];
        }
        rs0 += __shfl_xor_sync(~0u, rs0, 1);
        rs0 += __shfl_xor_sync(~0u, rs0, 2);
        rs1 += __shfl_xor_sync(~0u, rs1, 1);
        rs1 += __shfl_xor_sync(~0u, rs1, 2);
        l0 = l0 * sc0 + rs0;  l1 = l1 * sc1 + rs1;
        #pragma unroll
        for (int nb = 0; nb < 4; nb++) {
            oacc[nb][0] *= sc0; oacc[nb][1] *= sc0;
            oacc[nb][2] *= sc1; oacc[nb][3] *= sc1;
        }

        #pragma unroll
        for (int c = 0; c < 4; c++) {
            unsigned pah[4], pal[4];
            #pragma unroll
            for (int r4 = 0; r4 < 4; r4++) {
                int nb = 2 * c + (r4 >> 1);
                int pr = (r4 & 1) * 2;
                psplit2(sreg[nb][pr], sreg[nb][pr + 1], pah[r4], pal[r4]);
            }
            #pragma unroll
            for (int np = 0; np < 2; np++) {
                unsigned vh4[4], vl4[4];
                ldsm4(vh4, &Vs0[(np * 16 + brow) * VSTR + c * 16 + bcol]);
                ldsm4(vl4, &Vs1[(np * 16 + brow) * VSTR + c * 16 + bcol]);
                mma16816(oacc[2*np],   pah, vh4[0], vh4[1]);
                mma16816(oacc[2*np],   pal, vh4[0], vh4[1]);
                mma16816(oacc[2*np],   pah, vl4[0], vl4[1]);
                mma16816(oacc[2*np+1], pah, vh4[2], vh4[3]);
                mma16816(oacc[2*np+1], pal, vh4[2], vh4[3]);
                mma16816(oacc[2*np+1], pah, vl4[2], vl4[3]);
            }
        }
        __syncthreads();
    }

    int r = lane >> 2;
    int qg = q0 + w * 16 + r;
    if (split) {
        size_t pb = ((size_t)sp * 8 + bh) * HWY;
        #pragma unroll
        for (int nb = 0; nb < 4; nb++) {
            int d = nb * 8 + (lane & 3) * 2;
            *(float2*)&g_pacc[(pb + qg) * HD + d]     = make_float2(oacc[nb][0], oacc[nb][1]);
            *(float2*)&g_pacc[(pb + qg + 8) * HD + d] = make_float2(oacc[nb][2], oacc[nb][3]);
        }
        if ((lane & 3) == 0) {
            g_pml[pb + qg]     = make_float2(m0r, l0);
            g_pml[pb + qg + 8] = make_float2(m1r, l1);
        }
    } else {
        // write split bf16, TRANSPOSED [bh][d][q]  (c = h*32+d rows)
        float inv0 = 1.f / l0, inv1 = 1.f / l1;
        size_t ob = (size_t)bh * HD * NQ;
        #pragma unroll
        for (int nb = 0; nb < 4; nb++) {
            int d = nb * 8 + (lane & 3) * 2;
            bf16 hh, ll;
            bsplit(oacc[nb][0] * inv0, hh, ll);
            Oh_[ob + (size_t)d * NQ + qg] = hh;       Ol_[ob + (size_t)d * NQ + qg] = ll;
            bsplit(oacc[nb][1] * inv0, hh, ll);
            Oh_[ob + (size_t)(d+1) * NQ + qg] = hh;   Ol_[ob + (size_t)(d+1) * NQ + qg] = ll;
            bsplit(oacc[nb][2] * inv1, hh, ll);
            Oh_[ob + (size_t)d * NQ + qg + 8] = hh;   Ol_[ob + (size_t)d * NQ + qg + 8] = ll;
            bsplit(oacc[nb][3] * inv1, hh, ll);
            Oh_[ob + (size_t)(d+1) * NQ + qg + 8] = hh; Ol_[ob + (size_t)(d+1) * NQ + qg + 8] = ll;
        }
    }
}

// ====== combine split-K partials for dir1 -> split bf16 transposed ========
__global__ void __launch_bounds__(128) attn_combine_kernel()
{
    int t = blockIdx.x * 128 + threadIdx.x;   // 8192: (bh<8, q<1024)
    int bh = t >> 10, q = t & 1023;
    float2 ml[4];
    float M = -1e30f;
    #pragma unroll
    for (int s = 0; s < 4; s++) {
        ml[s] = g_pml[((size_t)s * 8 + bh) * HWY + q];
        M = fmaxf(M, ml[s].x);
    }
    float wgt[4], L = 0.f;
    #pragma unroll
    for (int s = 0; s < 4; s++) {
        wgt[s] = exp2f(ml[s].x - M);
        L += wgt[s] * ml[s].y;
    }
    float invL = 1.f / L;
    size_t ob = (size_t)bh * HD * HWY;
    #pragma unroll
    for (int d4 = 0; d4 < HD; d4 += 4) {
        float4 o = make_float4(0.f, 0.f, 0.f, 0.f);
        #pragma unroll
        for (int s = 0; s < 4; s++) {
            const float* a = g_pacc + (((size_t)s * 8 + bh) * HWY + q) * HD;
            float4 v = *(const float4*)(a + d4);
            o.x += wgt[s] * v.x;  o.y += wgt[s] * v.y;
            o.z += wgt[s] * v.z;  o.w += wgt[s] * v.w;
        }
        float vals[4] = {o.x * invL, o.y * invL, o.z * invL, o.w * invL};
        #pragma unroll
        for (int j = 0; j < 4; j++) {
            bf16 hh, ll; bsplit(vals[j], hh, ll);
            g_ayh[ob + (size_t)(d4 + j) * HWY + q] = hh;
            g_ayl[ob + (size_t)(d4 + j) * HWY + q] = ll;
        }
    }
}

// ============================== launcher ==================================
extern "C" void kernel_launch(void* const* d_in, const int* in_sizes, int n_in,
                              void* d_out, int out_size)
{
    (void)out_size;
    const float *x=0, *y=0, *wxq=0, *bxq=0, *wyq=0, *byq=0,
                *wpx=0, *bpx=0, *wpy=0, *bpy=0;
    for (int i = 0; i < n_in; i++) {
        const float* p = (const float*)d_in[i];
        switch (in_sizes[i]) {
            case 2097152: x = p;   break;
            case 1048576: y = p;   break;
            case 98304:   wxq = p; break;
            case 196608:  wyq = p; break;
            case 32768:   wpx = p; break;
            case 65536:   wpy = p; break;
            case 256:     bpx = p; break;
            case 512:     bpy = p; break;
            case 384:     if (!bxq) bxq = p; else byq = p; break;
            default: break;
        }
    }
    float* out = (float*)d_out;

    split_w_kernel<<<384, 256>>>(wxq, wyq, wpx, wpy);
    presplit_x_kernel<<<3072, 256>>>(x, y);
    qkv_mma5_kernel<<<480, 256>>>(bxq, byq);
    attn_mma_kernel<<<1024, 128>>>();
    attn_combine_kernel<<<64, 128>>>();
    proj_mma_kernel<<<384, 256>>>(bpx, x, bpy, y, out);
}